// round 3
// baseline (speedup 1.0000x reference)
#include <cuda_runtime.h>
#include <math.h>

#define Bn   2
#define Sn   1024
#define HIDn 2048
#define NHn  16
#define NSn  8
#define Dn   128
#define BSn  (Bn*Sn)    // 2048
#define BHn  (Bn*NHn)   // 32

// ---------------- scratch (device globals; no runtime alloc) ----------------
__device__ float g_Q[BSn*HIDn];
__device__ float g_K[BSn*HIDn];
__device__ float g_V[BSn*HIDn];
__device__ float g_CTX[BSn*HIDn];
__device__ float g_SC[(size_t)BHn*Sn*Sn];      // 128 MB scores/probs
__device__ float g_qa[BHn*Sn*NSn];
__device__ float g_ka[BHn*Sn*NSn];
__device__ float g_M[BHn*NSn*Dn];
__device__ float g_sk[BHn*NSn];
__device__ float g_pos[NHn*NSn*Dn];
__device__ float g_dir[NHn*NSn*Dn];
__device__ float g_possq[NHn*NSn];
__device__ float g_posdot[NHn*NSn];
__device__ float g_i2s2[NHn*NSn];
__device__ float g_amp[NHn*NSn];
__device__ float g_scal[2];                    // [0]=dir_strength sigmoid, [1]=blend

__device__ __forceinline__ float warp_sum(float v) {
#pragma unroll
    for (int o = 16; o > 0; o >>= 1) v += __shfl_xor_sync(0xffffffffu, v, o);
    return v;
}
__device__ __forceinline__ float warp_max(float v) {
#pragma unroll
    for (int o = 16; o > 0; o >>= 1) v = fmaxf(v, __shfl_xor_sync(0xffffffffu, v, o));
    return v;
}

// ---------------- splat parameter precompute (tiny) ----------------
__global__ void prep_kernel(const float* __restrict__ pos_in, const float* __restrict__ dir_in,
                            const float* __restrict__ lsc, const float* __restrict__ lam,
                            const float* __restrict__ dstr, const float* __restrict__ gstr)
{
    int i = threadIdx.x;  // 0..127 = h*NS+n
    const float eps = 1e-12f;
    const float* p  = pos_in + i * Dn;
    const float* dr = dir_in + i * Dn;
    float np = 0.f, nd = 0.f;
    for (int d = 0; d < Dn; d++) { np += p[d] * p[d]; nd += dr[d] * dr[d]; }
    np = sqrtf(np) + eps; nd = sqrtf(nd) + eps;
    const float sp = sqrtf((float)Dn) * 0.3f;
    float psq = 0.f, pd = 0.f;
    for (int d = 0; d < Dn; d++) {
        float pv = p[d] / np * sp;
        float dv = dr[d] / nd;
        g_pos[i * Dn + d] = pv;
        g_dir[i * Dn + d] = dv;
        psq += pv * pv; pd += pv * dv;
    }
    g_possq[i] = psq;
    g_posdot[i] = pd;
    float sc = expf(lsc[i]);
    sc = fminf(fmaxf(sc, 0.3f), 1.2f);
    g_i2s2[i] = 0.5f / (sc * sc);
    __syncthreads();
    if (i < NHn) {
        float mx = -1e30f;
        for (int n = 0; n < NSn; n++) mx = fmaxf(mx, lam[i * NSn + n]);
        float e[NSn], s = 0.f;
        for (int n = 0; n < NSn; n++) { e[n] = expf(lam[i * NSn + n] - mx); s += e[n]; }
        for (int n = 0; n < NSn; n++) g_amp[i * NSn + n] = e[n] / s;
    }
    if (i == 0) {
        g_scal[0] = 1.f / (1.f + expf(-dstr[0]));
        float gs  = 1.f / (1.f + expf(-gstr[0]));
        g_scal[1] = fminf(0.05f, gs * 0.1f);
    }
}

// ---- 2048x2048x2048 NN SGEMM: 128x128 tile, BK=16, double-buffered, 8x8 microtile ----
__device__ __forceinline__ void sgemm2048_body(const float* __restrict__ A,
                                               const float* __restrict__ B,
                                               float* __restrict__ C)
{
    const int N2 = 2048;
    __shared__ float As[2][16][132];   // As[buf][k][m], pad 132 to cut store conflicts
    __shared__ float Bs[2][16][128];   // Bs[buf][k][n]
    const int tid = threadIdx.x;
    const int crow = blockIdx.y * 128, ccol = blockIdx.x * 128;
    const int tx = tid & 15, ty = tid >> 4;

    // loader mapping: two float4 loads each for A-tile (128x16) and B-tile (16x128)
    const int arow0 = tid >> 2,         ac40 = (tid & 3) * 4;           // i=0
    const int arow1 = (tid + 256) >> 2, ac41 = ((tid + 256) & 3) * 4;   // i=1
    const int brow0 = tid >> 5,         bc40 = (tid & 31) * 4;
    const int brow1 = (tid + 256) >> 5, bc41 = ((tid + 256) & 31) * 4;

    const float* A0 = A + (size_t)(crow + arow0) * N2 + ac40;
    const float* A1 = A + (size_t)(crow + arow1) * N2 + ac41;
    const float* B0 = B + (size_t)brow0 * N2 + ccol + bc40;
    const float* B1 = B + (size_t)brow1 * N2 + ccol + bc41;

    float acc[8][8] = {};

    // preload tile 0 into buffer 0
    {
        float4 a0 = *(const float4*)A0;
        float4 a1 = *(const float4*)A1;
        float4 b0 = *(const float4*)B0;
        float4 b1 = *(const float4*)B1;
        As[0][ac40 + 0][arow0] = a0.x; As[0][ac40 + 1][arow0] = a0.y;
        As[0][ac40 + 2][arow0] = a0.z; As[0][ac40 + 3][arow0] = a0.w;
        As[0][ac41 + 0][arow1] = a1.x; As[0][ac41 + 1][arow1] = a1.y;
        As[0][ac41 + 2][arow1] = a1.z; As[0][ac41 + 3][arow1] = a1.w;
        *(float4*)&Bs[0][brow0][bc40] = b0;
        *(float4*)&Bs[0][brow1][bc41] = b1;
    }
    __syncthreads();

    int buf = 0;
    for (int k0 = 16; k0 < N2; k0 += 16) {
        // issue global loads for the NEXT tile (latency hidden behind compute below)
        float4 a0 = *(const float4*)(A0 + k0);
        float4 a1 = *(const float4*)(A1 + k0);
        float4 b0 = *(const float4*)(B0 + (size_t)k0 * N2);
        float4 b1 = *(const float4*)(B1 + (size_t)k0 * N2);

        // compute on current buffer
#pragma unroll
        for (int kk = 0; kk < 16; kk++) {
            float ra[8], rb[8];
#pragma unroll
            for (int m = 0; m < 8; m++) ra[m] = As[buf][kk][ty * 8 + m];
#pragma unroll
            for (int n = 0; n < 8; n++) rb[n] = Bs[buf][kk][tx * 8 + n];
#pragma unroll
            for (int m = 0; m < 8; m++)
#pragma unroll
                for (int n = 0; n < 8; n++) acc[m][n] += ra[m] * rb[n];
        }

        // store next tile into the other buffer
        const int nb = buf ^ 1;
        As[nb][ac40 + 0][arow0] = a0.x; As[nb][ac40 + 1][arow0] = a0.y;
        As[nb][ac40 + 2][arow0] = a0.z; As[nb][ac40 + 3][arow0] = a0.w;
        As[nb][ac41 + 0][arow1] = a1.x; As[nb][ac41 + 1][arow1] = a1.y;
        As[nb][ac41 + 2][arow1] = a1.z; As[nb][ac41 + 3][arow1] = a1.w;
        *(float4*)&Bs[nb][brow0][bc40] = b0;
        *(float4*)&Bs[nb][brow1][bc41] = b1;
        __syncthreads();
        buf = nb;
    }

    // final tile
#pragma unroll
    for (int kk = 0; kk < 16; kk++) {
        float ra[8], rb[8];
#pragma unroll
        for (int m = 0; m < 8; m++) ra[m] = As[buf][kk][ty * 8 + m];
#pragma unroll
        for (int n = 0; n < 8; n++) rb[n] = Bs[buf][kk][tx * 8 + n];
#pragma unroll
        for (int m = 0; m < 8; m++)
#pragma unroll
            for (int n = 0; n < 8; n++) acc[m][n] += ra[m] * rb[n];
    }

#pragma unroll
    for (int m = 0; m < 8; m++) {
        float* cp = C + (size_t)(crow + ty * 8 + m) * N2 + ccol + tx * 8;
#pragma unroll
        for (int n = 0; n < 8; n += 4)
            *(float4*)(cp + n) = make_float4(acc[m][n], acc[m][n+1], acc[m][n+2], acc[m][n+3]);
    }
}

// All three QKV projections in one launch: blockIdx.z selects {Wq,Wk,Wv}.
__global__ void __launch_bounds__(256) gemm_qkv(const float* __restrict__ X,
                                                const float* __restrict__ Wq,
                                                const float* __restrict__ Wk,
                                                const float* __restrict__ Wv)
{
    const int z = blockIdx.z;
    const float* W = (z == 0) ? Wq : (z == 1) ? Wk : Wv;
    float* C = (z == 0) ? g_Q : (z == 1) ? g_K : g_V;
    sgemm2048_body(X, W, C);
}

__global__ void __launch_bounds__(256) gemm_out(const float* __restrict__ Wo,
                                                float* __restrict__ out)
{
    sgemm2048_body(g_CTX, Wo, out);
}

// ---------------- scores = Q @ K^T / sqrt(D)  (NT, K=128) ----------------
__global__ void __launch_bounds__(256) attn_scores_kernel()
{
    const int bh = blockIdx.z;
    const int b = bh >> 4, h = bh & 15;
    const float* A  = g_Q + (size_t)b * Sn * HIDn + h * Dn;
    const float* Bm = g_K + (size_t)b * Sn * HIDn + h * Dn;
    float* C = g_SC + (size_t)bh * Sn * Sn;
    __shared__ float As[16][132];
    __shared__ float Bs[16][132];
    const int tid = threadIdx.x;
    const int crow = blockIdx.y * 128, ccol = blockIdx.x * 128;
    const int tx = tid & 15, ty = tid >> 4;
    float acc[8][8] = {};
    for (int k0 = 0; k0 < Dn; k0 += 16) {
#pragma unroll
        for (int i = 0; i < 2; i++) {
            int idx = tid + i * 256;        // 0..511 (float4 index)
            int row = idx >> 2;             // 0..127
            int c4  = (idx & 3) * 4;        // 0,4,8,12
            float4 av = *(const float4*)(A  + (size_t)(crow + row) * HIDn + k0 + c4);
            As[c4 + 0][row] = av.x; As[c4 + 1][row] = av.y;
            As[c4 + 2][row] = av.z; As[c4 + 3][row] = av.w;
            float4 bv = *(const float4*)(Bm + (size_t)(ccol + row) * HIDn + k0 + c4);
            Bs[c4 + 0][row] = bv.x; Bs[c4 + 1][row] = bv.y;
            Bs[c4 + 2][row] = bv.z; Bs[c4 + 3][row] = bv.w;
        }
        __syncthreads();
#pragma unroll
        for (int kk = 0; kk < 16; kk++) {
            float ra[8], rb[8];
#pragma unroll
            for (int m = 0; m < 8; m++) ra[m] = As[kk][ty * 8 + m];
#pragma unroll
            for (int n = 0; n < 8; n++) rb[n] = Bs[kk][tx * 8 + n];
#pragma unroll
            for (int m = 0; m < 8; m++)
#pragma unroll
                for (int n = 0; n < 8; n++) acc[m][n] += ra[m] * rb[n];
        }
        __syncthreads();
    }
    const float scale = 0.0883883476483184f;  // 1/sqrt(128)
#pragma unroll
    for (int m = 0; m < 8; m++) {
        float* cp = C + (size_t)(crow + ty * 8 + m) * Sn + ccol + tx * 8;
#pragma unroll
        for (int n = 0; n < 8; n += 4)
            *(float4*)(cp + n) = make_float4(acc[m][n] * scale, acc[m][n+1] * scale,
                                             acc[m][n+2] * scale, acc[m][n+3] * scale);
    }
}

// ---------------- row softmax over S=1024 (1 block / row) ----------------
__global__ void __launch_bounds__(256) softmax_kernel()
{
    const size_t row = blockIdx.x;
    float* p = g_SC + row * (size_t)Sn;
    const int tid = threadIdx.x;
    __shared__ float red[8];
    float4 v = ((float4*)p)[tid];
    float m = fmaxf(fmaxf(v.x, v.y), fmaxf(v.z, v.w));
    m = warp_max(m);
    if ((tid & 31) == 0) red[tid >> 5] = m;
    __syncthreads();
    float bm = red[0];
#pragma unroll
    for (int i = 1; i < 8; i++) bm = fmaxf(bm, red[i]);
    __syncthreads();
    v.x = expf(v.x - bm); v.y = expf(v.y - bm);
    v.z = expf(v.z - bm); v.w = expf(v.w - bm);
    float s = warp_sum(v.x + v.y + v.z + v.w);
    if ((tid & 31) == 0) red[tid >> 5] = s;
    __syncthreads();
    float bs = 0.f;
#pragma unroll
    for (int i = 0; i < 8; i++) bs += red[i];
    float inv = 1.f / bs;
    v.x *= inv; v.y *= inv; v.z *= inv; v.w *= inv;
    ((float4*)p)[tid] = v;
}

// ---------------- splat affinities: one warp per token; z selects Q/K ----------------
__global__ void __launch_bounds__(256) affinity_kernel()
{
    const int which = blockIdx.z;
    const float* T = (which == 0) ? g_Q : g_K;
    float* out = (which == 0) ? g_qa : g_ka;
    const int lane = threadIdx.x & 31;
    const int token = blockIdx.x * 8 + (threadIdx.x >> 5);
    if (token >= BHn * Sn) return;
    const int s = token & (Sn - 1);
    const int bh = token >> 10;
    const int h = bh & (NHn - 1), b = bh >> 4;
    const float* x = T + (size_t)(b * Sn + s) * HIDn + h * Dn;
    float x0 = x[lane], x1 = x[lane + 32], x2 = x[lane + 64], x3 = x[lane + 96];
    float tsq = warp_sum(x0 * x0 + x1 * x1 + x2 * x2 + x3 * x3);
    float ds = g_scal[0];
#pragma unroll
    for (int n = 0; n < NSn; n++) {
        const int hn = h * NSn + n;
        const float* pp = g_pos + hn * Dn;
        const float* dd = g_dir + hn * Dn;
        float tp = warp_sum(x0 * pp[lane] + x1 * pp[lane + 32] + x2 * pp[lane + 64] + x3 * pp[lane + 96]);
        float xd = warp_sum(x0 * dd[lane] + x1 * dd[lane + 32] + x2 * dd[lane + 64] + x3 * dd[lane + 96]);
        float dist2 = fmaxf(tsq - 2.f * tp + g_possq[hn], 0.f);
        float proj  = xd - g_posdot[hn];
        float perp2 = fmaxf(dist2 - proj * proj, 0.f);
        float i2 = g_i2s2[hn];
        float aff = (1.f - ds) * expf(-dist2 * i2) + ds * expf(-perp2 * i2);
        if (lane == 0) out[(size_t)token * NSn + n] = aff;
    }
}

// ---------------- M[n,:] = sum_s ka[s,n] * v[s,:], s_k[n] = sum_s ka[s,n] ----------------
__global__ void __launch_bounds__(128) ksum_kernel()
{
    const int idx = blockIdx.x;            // bh*NS+n, 0..255
    const int n = idx & 7, bh = idx >> 3;
    const int h = bh & 15, b = bh >> 4;
    const int d = threadIdx.x;
    const float* vb = g_V + (size_t)b * Sn * HIDn + h * Dn + d;
    const float* kb = g_ka + (size_t)bh * Sn * NSn + n;
    float acc = 0.f, ska = 0.f;
    for (int s = 0; s < Sn; s += 4) {
        float k0 = kb[(size_t)(s + 0) * NSn];
        float k1 = kb[(size_t)(s + 1) * NSn];
        float k2 = kb[(size_t)(s + 2) * NSn];
        float k3 = kb[(size_t)(s + 3) * NSn];
        acc += k0 * vb[(size_t)(s + 0) * HIDn];
        acc += k1 * vb[(size_t)(s + 1) * HIDn];
        acc += k2 * vb[(size_t)(s + 2) * HIDn];
        acc += k3 * vb[(size_t)(s + 3) * HIDn];
        ska += k0 + k1 + k2 + k3;
    }
    g_M[(size_t)idx * Dn + d] = acc;
    if (d == 0) g_sk[idx] = ska;
}

// ---------------- ctx = (1-blend)*(P@V) + blend*dgsa  (NN, N=128) ----------------
__global__ void __launch_bounds__(256) attn_pv_kernel()
{
    const int bh = blockIdx.z;
    const int b = bh >> 4, h = bh & 15;
    const float* A  = g_SC + (size_t)bh * Sn * Sn;
    const float* Bm = g_V + (size_t)b * Sn * HIDn + h * Dn;
    float* C = g_CTX + (size_t)b * Sn * HIDn + h * Dn;
    __shared__ float As[8][128];
    __shared__ float Bs[8][128];
    __shared__ float Msm[8][128];
    __shared__ float ampsm[8], sksm[8];
    const int tid = threadIdx.x;
    for (int i = tid; i < NSn * Dn; i += 256)
        Msm[i >> 7][i & 127] = g_M[(size_t)bh * NSn * Dn + i];
    if (tid < 8) { ampsm[tid] = g_amp[h * NSn + tid]; sksm[tid] = g_sk[bh * NSn + tid]; }
    const int crow = blockIdx.y * 128;
    const int tx = tid & 15, ty = tid >> 4;
    const int arow = tid >> 1,  ac4 = (tid & 1) * 4;
    const int brow = tid >> 5,  bc4 = (tid & 31) * 4;
    const float* Ap = A + (size_t)(crow + arow) * Sn + ac4;
    const float* Bp = Bm + (size_t)brow * HIDn + bc4;
    float acc[8][8] = {};
    __syncthreads();
    for (int k0 = 0; k0 < Sn; k0 += 8) {
        float4 av = *(const float4*)Ap;
        float4 bv = *(const float4*)Bp;
        As[ac4 + 0][arow] = av.x; As[ac4 + 1][arow] = av.y;
        As[ac4 + 2][arow] = av.z; As[ac4 + 3][arow] = av.w;
        *(float4*)&Bs[brow][bc4] = bv;
        __syncthreads();
#pragma unroll
        for (int kk = 0; kk < 8; kk++) {
            float ra[8], rb[8];
#pragma unroll
            for (int m = 0; m < 8; m++) ra[m] = As[kk][ty * 8 + m];
#pragma unroll
            for (int n = 0; n < 8; n++) rb[n] = Bs[kk][tx * 8 + n];
#pragma unroll
            for (int m = 0; m < 8; m++)
#pragma unroll
                for (int n = 0; n < 8; n++) acc[m][n] += ra[m] * rb[n];
        }
        __syncthreads();
        Ap += 8;
        Bp += (size_t)8 * HIDn;
    }
    const float blend = g_scal[1];
#pragma unroll
    for (int m = 0; m < 8; m++) {
        const int q = crow + ty * 8 + m;
        float wq[8];
        float den = 1e-8f;
#pragma unroll
        for (int n = 0; n < 8; n++) {
            wq[n] = g_qa[((size_t)bh * Sn + q) * NSn + n] * ampsm[n];
            den += wq[n] * sksm[n];
        }
        const float invden = 1.f / den;
        float* cp = C + (size_t)q * HIDn + tx * 8;
#pragma unroll
        for (int j = 0; j < 8; j++) {
            const int dcol = tx * 8 + j;
            float dg = 0.f;
#pragma unroll
            for (int n = 0; n < 8; n++) dg += wq[n] * Msm[n][dcol];
            dg *= invden;
            cp[j] = (1.f - blend) * acc[m][j] + blend * dg;
        }
    }
}

// ---------------- launch ----------------
extern "C" void kernel_launch(void* const* d_in, const int* in_sizes, int n_in,
                              void* d_out, int out_size)
{
    (void)in_sizes; (void)n_in; (void)out_size;
    const float* hs   = (const float*)d_in[0];
    const float* Wq   = (const float*)d_in[1];
    const float* Wk   = (const float*)d_in[2];
    const float* Wv   = (const float*)d_in[3];
    const float* Wo   = (const float*)d_in[4];
    const float* spos = (const float*)d_in[5];
    const float* sdir = (const float*)d_in[6];
    const float* lsc  = (const float*)d_in[7];
    const float* lam  = (const float*)d_in[8];
    const float* dstr = (const float*)d_in[9];
    const float* gstr = (const float*)d_in[10];
    float* out = (float*)d_out;

    prep_kernel<<<1, 128>>>(spos, sdir, lsc, lam, dstr, gstr);
    gemm_qkv<<<dim3(16, 16, 3), 256>>>(hs, Wq, Wk, Wv);
    attn_scores_kernel<<<dim3(8, 8, 32), 256>>>();
    softmax_kernel<<<32768, 256>>>();
    affinity_kernel<<<dim3(4096, 1, 2), 256>>>();
    ksum_kernel<<<256, 128>>>();
    attn_pv_kernel<<<dim3(1, 8, 32), 256>>>();
    gemm_out<<<dim3(16, 16), 256>>>(Wo, out);
}

// round 5
// speedup vs baseline: 2.4046x; 2.4046x over previous
#include <cuda_runtime.h>
#include <math.h>
#include <stdint.h>

#define Bn   2
#define Sn   1024
#define HIDn 2048
#define NHn  16
#define NSn  8
#define Dn   128
#define BSn  (Bn*Sn)    // 2048
#define BHn  (Bn*NHn)   // 32

// ---------------- scratch (device globals; no runtime alloc) ----------------
__device__ float g_Q[BSn*HIDn];
__device__ float g_K[BSn*HIDn];
__device__ float g_V[BSn*HIDn];
__device__ float g_CTX[BSn*HIDn];
__device__ float g_SC[(size_t)BHn*Sn*Sn];      // 128 MB scores/probs
__device__ float g_qa[BHn*Sn*NSn];
__device__ float g_ka[BHn*Sn*NSn];
__device__ float g_M[BHn*NSn*Dn];
__device__ float g_sk[BHn*NSn];
__device__ float g_pos[NHn*NSn*Dn];
__device__ float g_dir[NHn*NSn*Dn];
__device__ float g_possq[NHn*NSn];
__device__ float g_posdot[NHn*NSn];
__device__ float g_i2s2[NHn*NSn];
__device__ float g_amp[NHn*NSn];
__device__ float g_scal[2];                    // [0]=dir_strength sigmoid, [1]=blend

__device__ __forceinline__ float warp_sum(float v) {
#pragma unroll
    for (int o = 16; o > 0; o >>= 1) v += __shfl_xor_sync(0xffffffffu, v, o);
    return v;
}
__device__ __forceinline__ float warp_max(float v) {
#pragma unroll
    for (int o = 16; o > 0; o >>= 1) v = fmaxf(v, __shfl_xor_sync(0xffffffffu, v, o));
    return v;
}

// ---------------- tf32 mma primitives ----------------
__device__ __forceinline__ uint32_t f2tf32(float x) {
    uint32_t r;
    asm("cvt.rna.tf32.f32 %0, %1;" : "=r"(r) : "f"(x));
    return r;
}

__device__ __forceinline__ void mma8(float* c, const uint32_t* a, const uint32_t* b) {
    asm volatile(
        "mma.sync.aligned.m16n8k8.row.col.f32.tf32.tf32.f32 "
        "{%0,%1,%2,%3}, {%4,%5,%6,%7}, {%8,%9}, {%0,%1,%2,%3};"
        : "+f"(c[0]), "+f"(c[1]), "+f"(c[2]), "+f"(c[3])
        : "r"(a[0]), "r"(a[1]), "r"(a[2]), "r"(a[3]), "r"(b[0]), "r"(b[1]));
}

// Compute 16 mma ops per warp over a BK=16 slab.
// As[k][m] (136-padded), Bs[k][n] (136-padded). Warp tile 64x32.
__device__ __forceinline__ void compute_bk16(const uint32_t (*As)[136], const uint32_t (*Bs)[136],
                                             float (&acc)[4][4][4],
                                             int wm, int wn, int g, int tig)
{
#pragma unroll
    for (int ks = 0; ks < 16; ks += 8) {
        uint32_t a[4][4], b[4][2];
#pragma unroll
        for (int mi = 0; mi < 4; mi++) {
            const int r = wm + mi * 16 + g;
            a[mi][0] = As[ks + tig][r];
            a[mi][1] = As[ks + tig][r + 8];
            a[mi][2] = As[ks + tig + 4][r];
            a[mi][3] = As[ks + tig + 4][r + 8];
        }
#pragma unroll
        for (int ni = 0; ni < 4; ni++) {
            const int c = wn + ni * 8 + g;
            b[ni][0] = Bs[ks + tig][c];
            b[ni][1] = Bs[ks + tig + 4][c];
        }
#pragma unroll
        for (int mi = 0; mi < 4; mi++)
#pragma unroll
            for (int ni = 0; ni < 4; ni++)
                mma8(acc[mi][ni], a[mi], b[ni]);
    }
}

// ---- NN mainloop: A row-major MxK (lda), B row-major KxN (ldb). 128x128 tile, BK=16, dbl-buffered.
__device__ __forceinline__ void mma_nn_loop(const float* __restrict__ Ag, int lda,
                                            const float* __restrict__ Bg, int ldb,
                                            int K, float (&acc)[4][4][4])
{
    __shared__ uint32_t As[2][16][136];
    __shared__ uint32_t Bs[2][16][136];
    const int tid = threadIdx.x;
    const int lane = tid & 31, wid = tid >> 5;
    const int g = lane >> 2, tig = lane & 3;
    const int wm = (wid >> 2) * 64, wn = (wid & 3) * 32;
    const int crow = blockIdx.y * 128, ccol = blockIdx.x * 128;
    const int ar = tid >> 2,  ak = (tid & 3) * 4;    // A scatter: rows ar, ar+64; k-cols ak..ak+3
    const int br = tid >> 5,  bc = (tid & 31) * 4;   // B direct: rows br, br+8; n-cols bc..bc+3
    const float* A0 = Ag + (size_t)(crow + ar) * lda + ak;
    const float* A1 = Ag + (size_t)(crow + ar + 64) * lda + ak;
    const float* B0 = Bg + (size_t)br * ldb + ccol + bc;
    const float* B1 = Bg + (size_t)(br + 8) * ldb + ccol + bc;

    // preload tile 0
    {
        float4 a0 = *(const float4*)A0;
        float4 a1 = *(const float4*)A1;
        float4 b0 = *(const float4*)B0;
        float4 b1 = *(const float4*)B1;
        As[0][ak + 0][ar] = f2tf32(a0.x); As[0][ak + 1][ar] = f2tf32(a0.y);
        As[0][ak + 2][ar] = f2tf32(a0.z); As[0][ak + 3][ar] = f2tf32(a0.w);
        As[0][ak + 0][ar + 64] = f2tf32(a1.x); As[0][ak + 1][ar + 64] = f2tf32(a1.y);
        As[0][ak + 2][ar + 64] = f2tf32(a1.z); As[0][ak + 3][ar + 64] = f2tf32(a1.w);
        uint4 pb0 = make_uint4(f2tf32(b0.x), f2tf32(b0.y), f2tf32(b0.z), f2tf32(b0.w));
        uint4 pb1 = make_uint4(f2tf32(b1.x), f2tf32(b1.y), f2tf32(b1.z), f2tf32(b1.w));
        *(uint4*)&Bs[0][br][bc] = pb0;
        *(uint4*)&Bs[0][br + 8][bc] = pb1;
    }
    __syncthreads();

    int buf = 0;
    for (int k0 = 16; k0 < K; k0 += 16) {
        float4 a0 = *(const float4*)(A0 + k0);
        float4 a1 = *(const float4*)(A1 + k0);
        float4 b0 = *(const float4*)(B0 + (size_t)k0 * ldb);
        float4 b1 = *(const float4*)(B1 + (size_t)k0 * ldb);

        compute_bk16(As[buf], Bs[buf], acc, wm, wn, g, tig);

        const int nb = buf ^ 1;
        As[nb][ak + 0][ar] = f2tf32(a0.x); As[nb][ak + 1][ar] = f2tf32(a0.y);
        As[nb][ak + 2][ar] = f2tf32(a0.z); As[nb][ak + 3][ar] = f2tf32(a0.w);
        As[nb][ak + 0][ar + 64] = f2tf32(a1.x); As[nb][ak + 1][ar + 64] = f2tf32(a1.y);
        As[nb][ak + 2][ar + 64] = f2tf32(a1.z); As[nb][ak + 3][ar + 64] = f2tf32(a1.w);
        uint4 pb0 = make_uint4(f2tf32(b0.x), f2tf32(b0.y), f2tf32(b0.z), f2tf32(b0.w));
        uint4 pb1 = make_uint4(f2tf32(b1.x), f2tf32(b1.y), f2tf32(b1.z), f2tf32(b1.w));
        *(uint4*)&Bs[nb][br][bc] = pb0;
        *(uint4*)&Bs[nb][br + 8][bc] = pb1;
        __syncthreads();
        buf = nb;
    }
    compute_bk16(As[buf], Bs[buf], acc, wm, wn, g, tig);
}

// ---- NT mainloop: A row-major MxK (lda), B rows are the N dim: B[n][k] (ldb). (C = A @ B^T)
__device__ __forceinline__ void mma_nt_loop(const float* __restrict__ Ag, int lda,
                                            const float* __restrict__ Bg, int ldb,
                                            int K, float (&acc)[4][4][4])
{
    __shared__ uint32_t As[2][16][136];
    __shared__ uint32_t Bs[2][16][136];
    const int tid = threadIdx.x;
    const int lane = tid & 31, wid = tid >> 5;
    const int g = lane >> 2, tig = lane & 3;
    const int wm = (wid >> 2) * 64, wn = (wid & 3) * 32;
    const int crow = blockIdx.y * 128, ccol = blockIdx.x * 128;
    const int ar = tid >> 2, ak = (tid & 3) * 4;
    const float* A0 = Ag + (size_t)(crow + ar) * lda + ak;
    const float* A1 = Ag + (size_t)(crow + ar + 64) * lda + ak;
    const float* B0 = Bg + (size_t)(ccol + ar) * ldb + ak;
    const float* B1 = Bg + (size_t)(ccol + ar + 64) * ldb + ak;

    {
        float4 a0 = *(const float4*)A0;
        float4 a1 = *(const float4*)A1;
        float4 b0 = *(const float4*)B0;
        float4 b1 = *(const float4*)B1;
        As[0][ak + 0][ar] = f2tf32(a0.x); As[0][ak + 1][ar] = f2tf32(a0.y);
        As[0][ak + 2][ar] = f2tf32(a0.z); As[0][ak + 3][ar] = f2tf32(a0.w);
        As[0][ak + 0][ar + 64] = f2tf32(a1.x); As[0][ak + 1][ar + 64] = f2tf32(a1.y);
        As[0][ak + 2][ar + 64] = f2tf32(a1.z); As[0][ak + 3][ar + 64] = f2tf32(a1.w);
        Bs[0][ak + 0][ar] = f2tf32(b0.x); Bs[0][ak + 1][ar] = f2tf32(b0.y);
        Bs[0][ak + 2][ar] = f2tf32(b0.z); Bs[0][ak + 3][ar] = f2tf32(b0.w);
        Bs[0][ak + 0][ar + 64] = f2tf32(b1.x); Bs[0][ak + 1][ar + 64] = f2tf32(b1.y);
        Bs[0][ak + 2][ar + 64] = f2tf32(b1.z); Bs[0][ak + 3][ar + 64] = f2tf32(b1.w);
    }
    __syncthreads();

    int buf = 0;
    for (int k0 = 16; k0 < K; k0 += 16) {
        float4 a0 = *(const float4*)(A0 + k0);
        float4 a1 = *(const float4*)(A1 + k0);
        float4 b0 = *(const float4*)(B0 + k0);
        float4 b1 = *(const float4*)(B1 + k0);

        compute_bk16(As[buf], Bs[buf], acc, wm, wn, g, tig);

        const int nb = buf ^ 1;
        As[nb][ak + 0][ar] = f2tf32(a0.x); As[nb][ak + 1][ar] = f2tf32(a0.y);
        As[nb][ak + 2][ar] = f2tf32(a0.z); As[nb][ak + 3][ar] = f2tf32(a0.w);
        As[nb][ak + 0][ar + 64] = f2tf32(a1.x); As[nb][ak + 1][ar + 64] = f2tf32(a1.y);
        As[nb][ak + 2][ar + 64] = f2tf32(a1.z); As[nb][ak + 3][ar + 64] = f2tf32(a1.w);
        Bs[nb][ak + 0][ar] = f2tf32(b0.x); Bs[nb][ak + 1][ar] = f2tf32(b0.y);
        Bs[nb][ak + 2][ar] = f2tf32(b0.z); Bs[nb][ak + 3][ar] = f2tf32(b0.w);
        Bs[nb][ak + 0][ar + 64] = f2tf32(b1.x); Bs[nb][ak + 1][ar + 64] = f2tf32(b1.y);
        Bs[nb][ak + 2][ar + 64] = f2tf32(b1.z); Bs[nb][ak + 3][ar + 64] = f2tf32(b1.w);
        __syncthreads();
        buf = nb;
    }
    compute_bk16(As[buf], Bs[buf], acc, wm, wn, g, tig);
}

// generic epilogue: store acc (optionally scaled) to C (ldc)
__device__ __forceinline__ void store_tile(float* __restrict__ C, int ldc, float scale,
                                           const float (&acc)[4][4][4])
{
    const int tid = threadIdx.x;
    const int lane = tid & 31, wid = tid >> 5;
    const int g = lane >> 2, tig = lane & 3;
    const int wm = (wid >> 2) * 64, wn = (wid & 3) * 32;
    const int crow = blockIdx.y * 128, ccol = blockIdx.x * 128;
#pragma unroll
    for (int mi = 0; mi < 4; mi++) {
        const int r = crow + wm + mi * 16 + g;
#pragma unroll
        for (int ni = 0; ni < 4; ni++) {
            const int c = ccol + wn + ni * 8 + 2 * tig;
            *(float2*)&C[(size_t)r * ldc + c] =
                make_float2(acc[mi][ni][0] * scale, acc[mi][ni][1] * scale);
            *(float2*)&C[(size_t)(r + 8) * ldc + c] =
                make_float2(acc[mi][ni][2] * scale, acc[mi][ni][3] * scale);
        }
    }
}

// ---------------- splat parameter precompute (tiny) ----------------
__global__ void prep_kernel(const float* __restrict__ pos_in, const float* __restrict__ dir_in,
                            const float* __restrict__ lsc, const float* __restrict__ lam,
                            const float* __restrict__ dstr, const float* __restrict__ gstr)
{
    int i = threadIdx.x;  // 0..127 = h*NS+n
    const float eps = 1e-12f;
    const float* p  = pos_in + i * Dn;
    const float* dr = dir_in + i * Dn;
    float np = 0.f, nd = 0.f;
    for (int d = 0; d < Dn; d++) { np += p[d] * p[d]; nd += dr[d] * dr[d]; }
    np = sqrtf(np) + eps; nd = sqrtf(nd) + eps;
    const float sp = sqrtf((float)Dn) * 0.3f;
    float psq = 0.f, pd = 0.f;
    for (int d = 0; d < Dn; d++) {
        float pv = p[d] / np * sp;
        float dv = dr[d] / nd;
        g_pos[i * Dn + d] = pv;
        g_dir[i * Dn + d] = dv;
        psq += pv * pv; pd += pv * dv;
    }
    g_possq[i] = psq;
    g_posdot[i] = pd;
    float sc = expf(lsc[i]);
    sc = fminf(fmaxf(sc, 0.3f), 1.2f);
    g_i2s2[i] = 0.5f / (sc * sc);
    __syncthreads();
    if (i < NHn) {
        float mx = -1e30f;
        for (int n = 0; n < NSn; n++) mx = fmaxf(mx, lam[i * NSn + n]);
        float e[NSn], s = 0.f;
        for (int n = 0; n < NSn; n++) { e[n] = expf(lam[i * NSn + n] - mx); s += e[n]; }
        for (int n = 0; n < NSn; n++) g_amp[i * NSn + n] = e[n] / s;
    }
    if (i == 0) {
        g_scal[0] = 1.f / (1.f + expf(-dstr[0]));
        float gs  = 1.f / (1.f + expf(-gstr[0]));
        g_scal[1] = fminf(0.05f, gs * 0.1f);
    }
}

// ---------------- big GEMMs (tf32 tensor) ----------------
__global__ void __launch_bounds__(256, 2) gemm_qkv(const float* __restrict__ X,
                                                   const float* __restrict__ Wq,
                                                   const float* __restrict__ Wk,
                                                   const float* __restrict__ Wv)
{
    const int z = blockIdx.z;
    const float* W = (z == 0) ? Wq : (z == 1) ? Wk : Wv;
    float* C = (z == 0) ? g_Q : (z == 1) ? g_K : g_V;
    float acc[4][4][4] = {};
    mma_nn_loop(X, HIDn, W, HIDn, HIDn, acc);
    store_tile(C, HIDn, 1.0f, acc);
}

__global__ void __launch_bounds__(256, 2) gemm_out(const float* __restrict__ Wo,
                                                   float* __restrict__ out)
{
    float acc[4][4][4] = {};
    mma_nn_loop(g_CTX, HIDn, Wo, HIDn, HIDn, acc);
    store_tile(out, HIDn, 1.0f, acc);
}

// ---------------- scores = Q @ K^T / sqrt(D)  (tf32 NT) ----------------
__global__ void __launch_bounds__(256, 2) attn_scores_kernel()
{
    const int bh = blockIdx.z;
    const int b = bh >> 4, h = bh & 15;
    const float* A  = g_Q + (size_t)b * Sn * HIDn + h * Dn;
    const float* Bm = g_K + (size_t)b * Sn * HIDn + h * Dn;
    float* C = g_SC + (size_t)bh * Sn * Sn;
    float acc[4][4][4] = {};
    mma_nt_loop(A, HIDn, Bm, HIDn, Dn, acc);
    store_tile(C, Sn, 0.0883883476483184f, acc);   // 1/sqrt(128)
}

// ---------------- row softmax over S=1024 (1 block / row) ----------------
__global__ void __launch_bounds__(256) softmax_kernel()
{
    const size_t row = blockIdx.x;
    float* p = g_SC + row * (size_t)Sn;
    const int tid = threadIdx.x;
    __shared__ float red[8];
    float4 v = ((float4*)p)[tid];
    float m = fmaxf(fmaxf(v.x, v.y), fmaxf(v.z, v.w));
    m = warp_max(m);
    if ((tid & 31) == 0) red[tid >> 5] = m;
    __syncthreads();
    float bm = red[0];
#pragma unroll
    for (int i = 1; i < 8; i++) bm = fmaxf(bm, red[i]);
    __syncthreads();
    v.x = expf(v.x - bm); v.y = expf(v.y - bm);
    v.z = expf(v.z - bm); v.w = expf(v.w - bm);
    float s = warp_sum(v.x + v.y + v.z + v.w);
    if ((tid & 31) == 0) red[tid >> 5] = s;
    __syncthreads();
    float bs = 0.f;
#pragma unroll
    for (int i = 0; i < 8; i++) bs += red[i];
    float inv = 1.f / bs;
    v.x *= inv; v.y *= inv; v.z *= inv; v.w *= inv;
    ((float4*)p)[tid] = v;
}

// ---------------- splat affinities: one warp per token; z selects Q/K ----------------
__global__ void __launch_bounds__(256) affinity_kernel()
{
    const int which = blockIdx.z;
    const float* T = (which == 0) ? g_Q : g_K;
    float* out = (which == 0) ? g_qa : g_ka;
    const int lane = threadIdx.x & 31;
    const int token = blockIdx.x * 8 + (threadIdx.x >> 5);
    if (token >= BHn * Sn) return;
    const int s = token & (Sn - 1);
    const int bh = token >> 10;
    const int h = bh & (NHn - 1), b = bh >> 4;
    const float* x = T + (size_t)(b * Sn + s) * HIDn + h * Dn;
    float x0 = x[lane], x1 = x[lane + 32], x2 = x[lane + 64], x3 = x[lane + 96];
    float tsq = warp_sum(x0 * x0 + x1 * x1 + x2 * x2 + x3 * x3);
    float ds = g_scal[0];
#pragma unroll
    for (int n = 0; n < NSn; n++) {
        const int hn = h * NSn + n;
        const float* pp = g_pos + hn * Dn;
        const float* dd = g_dir + hn * Dn;
        float tp = warp_sum(x0 * pp[lane] + x1 * pp[lane + 32] + x2 * pp[lane + 64] + x3 * pp[lane + 96]);
        float xd = warp_sum(x0 * dd[lane] + x1 * dd[lane + 32] + x2 * dd[lane + 64] + x3 * dd[lane + 96]);
        float dist2 = fmaxf(tsq - 2.f * tp + g_possq[hn], 0.f);
        float proj  = xd - g_posdot[hn];
        float perp2 = fmaxf(dist2 - proj * proj, 0.f);
        float i2 = g_i2s2[hn];
        float aff = (1.f - ds) * expf(-dist2 * i2) + ds * expf(-perp2 * i2);
        if (lane == 0) out[(size_t)token * NSn + n] = aff;
    }
}

// ---------------- M[n,:] = sum_s ka[s,n] * v[s,:], s_k[n] = sum_s ka[s,n] ----------------
__global__ void __launch_bounds__(128) ksum_kernel()
{
    const int idx = blockIdx.x;            // bh*NS+n, 0..255
    const int n = idx & 7, bh = idx >> 3;
    const int h = bh & 15, b = bh >> 4;
    const int d = threadIdx.x;
    const float* vb = g_V + (size_t)b * Sn * HIDn + h * Dn + d;
    const float* kb = g_ka + (size_t)bh * Sn * NSn + n;
    float acc = 0.f, ska = 0.f;
    for (int s = 0; s < Sn; s += 4) {
        float k0 = kb[(size_t)(s + 0) * NSn];
        float k1 = kb[(size_t)(s + 1) * NSn];
        float k2 = kb[(size_t)(s + 2) * NSn];
        float k3 = kb[(size_t)(s + 3) * NSn];
        acc += k0 * vb[(size_t)(s + 0) * HIDn];
        acc += k1 * vb[(size_t)(s + 1) * HIDn];
        acc += k2 * vb[(size_t)(s + 2) * HIDn];
        acc += k3 * vb[(size_t)(s + 3) * HIDn];
        ska += k0 + k1 + k2 + k3;
    }
    g_M[(size_t)idx * Dn + d] = acc;
    if (d == 0) g_sk[idx] = ska;
}

// ---------------- ctx = (1-blend)*(P@V) + blend*dgsa  (tf32 NN + GSA epilogue) ----------------
__global__ void __launch_bounds__(256, 2) attn_pv_kernel()
{
    const int bh = blockIdx.z;
    const int b = bh >> 4, h = bh & 15;
    __shared__ float Msm[NSn][Dn];
    __shared__ float ampsm[NSn], sksm[NSn];
    const int tid = threadIdx.x;
    for (int i = tid; i < NSn * Dn; i += 256)
        Msm[i >> 7][i & 127] = g_M[(size_t)bh * NSn * Dn + i];
    if (tid < NSn) { ampsm[tid] = g_amp[h * NSn + tid]; sksm[tid] = g_sk[bh * NSn + tid]; }

    float acc[4][4][4] = {};
    mma_nn_loop(g_SC + (size_t)bh * Sn * Sn, Sn,
                g_V + (size_t)b * Sn * HIDn + h * Dn, HIDn, Sn, acc);

    const float blend = g_scal[1];
    const float ob = 1.f - blend;
    const int lane = tid & 31, wid = tid >> 5;
    const int g = lane >> 2, tig = lane & 3;
    const int wm = (wid >> 2) * 64, wn = (wid & 3) * 32;
    const int crow = blockIdx.y * 128;
    float* Cb = g_CTX + (size_t)b * Sn * HIDn + h * Dn;

#pragma unroll
    for (int mi = 0; mi < 4; mi++) {
#pragma unroll
        for (int half = 0; half < 2; half++) {
            const int r = crow + wm + mi * 16 + g + half * 8;
            const float4 qa0 = *(const float4*)&g_qa[((size_t)bh * Sn + r) * NSn];
            const float4 qa1 = *(const float4*)&g_qa[((size_t)bh * Sn + r) * NSn + 4];
            float wq[8];
            wq[0] = qa0.x * ampsm[0]; wq[1] = qa0.y * ampsm[1];
            wq[2] = qa0.z * ampsm[2]; wq[3] = qa0.w * ampsm[3];
            wq[4] = qa1.x * ampsm[4]; wq[5] = qa1.y * ampsm[5];
            wq[6] = qa1.z * ampsm[6]; wq[7] = qa1.w * ampsm[7];
            float den = 1e-8f;
#pragma unroll
            for (int n = 0; n < 8; n++) den += wq[n] * sksm[n];
            const float invden = 1.f / den;
#pragma unroll
            for (int ni = 0; ni < 4; ni++) {
                const int c = wn + ni * 8 + 2 * tig;
                float dg0 = 0.f, dg1 = 0.f;
#pragma unroll
                for (int n = 0; n < 8; n++) {
                    dg0 += wq[n] * Msm[n][c];
                    dg1 += wq[n] * Msm[n][c + 1];
                }
                const float a0 = acc[mi][ni][half * 2 + 0];
                const float a1 = acc[mi][ni][half * 2 + 1];
                *(float2*)&Cb[(size_t)r * HIDn + c] =
                    make_float2(ob * a0 + blend * dg0 * invden,
                                ob * a1 + blend * dg1 * invden);
            }
        }
    }
}

// ---------------- launch ----------------
extern "C" void kernel_launch(void* const* d_in, const int* in_sizes, int n_in,
                              void* d_out, int out_size)
{
    (void)in_sizes; (void)n_in; (void)out_size;
    const float* hs   = (const float*)d_in[0];
    const float* Wq   = (const float*)d_in[1];
    const float* Wk   = (const float*)d_in[2];
    const float* Wv   = (const float*)d_in[3];
    const float* Wo   = (const float*)d_in[4];
    const float* spos = (const float*)d_in[5];
    const float* sdir = (const float*)d_in[6];
    const float* lsc  = (const float*)d_in[7];
    const float* lam  = (const float*)d_in[8];
    const float* dstr = (const float*)d_in[9];
    const float* gstr = (const float*)d_in[10];
    float* out = (float*)d_out;

    prep_kernel<<<1, 128>>>(spos, sdir, lsc, lam, dstr, gstr);
    gemm_qkv<<<dim3(16, 16, 3), 256>>>(hs, Wq, Wk, Wv);
    attn_scores_kernel<<<dim3(8, 8, 32), 256>>>();
    softmax_kernel<<<32768, 256>>>();
    affinity_kernel<<<dim3(4096, 1, 2), 256>>>();
    ksum_kernel<<<256, 128>>>();
    attn_pv_kernel<<<dim3(1, 8, 32), 256>>>();
    gemm_out<<<dim3(16, 16), 256>>>(Wo, out);
}

// round 8
// speedup vs baseline: 2.5771x; 1.0717x over previous
#include <cuda_runtime.h>
#include <math.h>
#include <stdint.h>

#define Bn   2
#define Sn   1024
#define HIDn 2048
#define NHn  16
#define NSn  8
#define Dn   128
#define BSn  (Bn*Sn)    // 2048
#define BHn  (Bn*NHn)   // 32

// ---------------- scratch (device globals; no runtime alloc) ----------------
__device__ float g_Q[BSn*HIDn];
__device__ float g_K[BSn*HIDn];
__device__ float g_V[BSn*HIDn];
__device__ float g_CTX[BSn*HIDn];
__device__ float g_qa[BHn*Sn*NSn];
__device__ float g_ka[BHn*Sn*NSn];
__device__ float g_M[BHn*NSn*Dn];
__device__ float g_sk[BHn*NSn];
__device__ float g_pos[NHn*NSn*Dn];
__device__ float g_dir[NHn*NSn*Dn];
__device__ float g_possq[NHn*NSn];
__device__ float g_posdot[NHn*NSn];
__device__ float g_i2s2[NHn*NSn];
__device__ float g_amp[NHn*NSn];
__device__ float g_scal[2];                    // [0]=dir_strength sigmoid, [1]=blend

__device__ __forceinline__ float warp_sum(float v) {
#pragma unroll
    for (int o = 16; o > 0; o >>= 1) v += __shfl_xor_sync(0xffffffffu, v, o);
    return v;
}

// ---------------- tf32 mma primitives ----------------
__device__ __forceinline__ uint32_t f2tf32(float x) {
    uint32_t r;
    asm("cvt.rna.tf32.f32 %0, %1;" : "=r"(r) : "f"(x));
    return r;
}

__device__ __forceinline__ void mma8(float* c, const uint32_t* a, const uint32_t* b) {
    asm volatile(
        "mma.sync.aligned.m16n8k8.row.col.f32.tf32.tf32.f32 "
        "{%0,%1,%2,%3}, {%4,%5,%6,%7}, {%8,%9}, {%0,%1,%2,%3};"
        : "+f"(c[0]), "+f"(c[1]), "+f"(c[2]), "+f"(c[3])
        : "r"(a[0]), "r"(a[1]), "r"(a[2]), "r"(a[3]), "r"(b[0]), "r"(b[1]));
}

// Compute 32 mma ops per warp over a BK=16 slab. As/Bs stride 136 words.
__device__ __forceinline__ void compute_slab16(const uint32_t* __restrict__ As,
                                               const uint32_t* __restrict__ Bs,
                                               float (&acc)[4][4][4],
                                               int wm, int wn, int g, int tig)
{
#pragma unroll
    for (int ks = 0; ks < 16; ks += 8) {
        uint32_t a[4][4], b[4][2];
#pragma unroll
        for (int mi = 0; mi < 4; mi++) {
            const int r = wm + mi * 16 + g;
            a[mi][0] = As[(ks + tig) * 136 + r];
            a[mi][1] = As[(ks + tig) * 136 + r + 8];
            a[mi][2] = As[(ks + tig + 4) * 136 + r];
            a[mi][3] = As[(ks + tig + 4) * 136 + r + 8];
        }
#pragma unroll
        for (int ni = 0; ni < 4; ni++) {
            const int c = wn + ni * 8 + g;
            b[ni][0] = Bs[(ks + tig) * 136 + c];
            b[ni][1] = Bs[(ks + tig + 4) * 136 + c];
        }
#pragma unroll
        for (int mi = 0; mi < 4; mi++)
#pragma unroll
            for (int ni = 0; ni < 4; ni++)
                mma8(acc[mi][ni], a[mi], b[ni]);
    }
}

// scatter 2 float4 (k-major A layout): S[k][col], k = dbase..dbase+3 and +8..+11
__device__ __forceinline__ void stA_slab(uint32_t* S, int dbase, int col, float4 q0, float4 q1) {
    S[(dbase + 0) * 136 + col] = f2tf32(q0.x);
    S[(dbase + 1) * 136 + col] = f2tf32(q0.y);
    S[(dbase + 2) * 136 + col] = f2tf32(q0.z);
    S[(dbase + 3) * 136 + col] = f2tf32(q0.w);
    S[(dbase + 8) * 136 + col] = f2tf32(q1.x);
    S[(dbase + 9) * 136 + col] = f2tf32(q1.y);
    S[(dbase + 10) * 136 + col] = f2tf32(q1.z);
    S[(dbase + 11) * 136 + col] = f2tf32(q1.w);
}

// direct 2 uint4 (n-major B layout): S[r][c4..c4+3], rows r and r+8
__device__ __forceinline__ void stB_slab(uint32_t* S, int r, int c4, float4 v0, float4 v1) {
    uint4 p0 = make_uint4(f2tf32(v0.x), f2tf32(v0.y), f2tf32(v0.z), f2tf32(v0.w));
    uint4 p1 = make_uint4(f2tf32(v1.x), f2tf32(v1.y), f2tf32(v1.z), f2tf32(v1.w));
    *(uint4*)&S[r * 136 + c4] = p0;
    *(uint4*)&S[(r + 8) * 136 + c4] = p1;
}

// ---- NN mainloop (for 2048^3 GEMMs): 128x128 tile, BK=16, dbl-buffered ----
__device__ __forceinline__ void mma_nn_loop(const float* __restrict__ Ag, int lda,
                                            const float* __restrict__ Bg, int ldb,
                                            int K, float (&acc)[4][4][4])
{
    __shared__ uint32_t As[2][16][136];
    __shared__ uint32_t Bs[2][16][136];
    const int tid = threadIdx.x;
    const int lane = tid & 31, wid = tid >> 5;
    const int g = lane >> 2, tig = lane & 3;
    const int wm = (wid >> 2) * 64, wn = (wid & 3) * 32;
    const int crow = blockIdx.y * 128, ccol = blockIdx.x * 128;
    const int ar = tid >> 2,  ak = (tid & 3) * 4;
    const int br = tid >> 5,  bc = (tid & 31) * 4;
    const float* A0 = Ag + (size_t)(crow + ar) * lda + ak;
    const float* A1 = Ag + (size_t)(crow + ar + 64) * lda + ak;
    const float* B0 = Bg + (size_t)br * ldb + ccol + bc;
    const float* B1 = Bg + (size_t)(br + 8) * ldb + ccol + bc;

    {
        float4 a0 = *(const float4*)A0;
        float4 a1 = *(const float4*)A1;
        float4 b0 = *(const float4*)B0;
        float4 b1 = *(const float4*)B1;
        As[0][ak + 0][ar] = f2tf32(a0.x); As[0][ak + 1][ar] = f2tf32(a0.y);
        As[0][ak + 2][ar] = f2tf32(a0.z); As[0][ak + 3][ar] = f2tf32(a0.w);
        As[0][ak + 0][ar + 64] = f2tf32(a1.x); As[0][ak + 1][ar + 64] = f2tf32(a1.y);
        As[0][ak + 2][ar + 64] = f2tf32(a1.z); As[0][ak + 3][ar + 64] = f2tf32(a1.w);
        uint4 pb0 = make_uint4(f2tf32(b0.x), f2tf32(b0.y), f2tf32(b0.z), f2tf32(b0.w));
        uint4 pb1 = make_uint4(f2tf32(b1.x), f2tf32(b1.y), f2tf32(b1.z), f2tf32(b1.w));
        *(uint4*)&Bs[0][br][bc] = pb0;
        *(uint4*)&Bs[0][br + 8][bc] = pb1;
    }
    __syncthreads();

    int buf = 0;
    for (int k0 = 16; k0 < K; k0 += 16) {
        float4 a0 = *(const float4*)(A0 + k0);
        float4 a1 = *(const float4*)(A1 + k0);
        float4 b0 = *(const float4*)(B0 + (size_t)k0 * ldb);
        float4 b1 = *(const float4*)(B1 + (size_t)k0 * ldb);

        compute_slab16(&As[buf][0][0], &Bs[buf][0][0], acc, wm, wn, g, tig);

        const int nb = buf ^ 1;
        As[nb][ak + 0][ar] = f2tf32(a0.x); As[nb][ak + 1][ar] = f2tf32(a0.y);
        As[nb][ak + 2][ar] = f2tf32(a0.z); As[nb][ak + 3][ar] = f2tf32(a0.w);
        As[nb][ak + 0][ar + 64] = f2tf32(a1.x); As[nb][ak + 1][ar + 64] = f2tf32(a1.y);
        As[nb][ak + 2][ar + 64] = f2tf32(a1.z); As[nb][ak + 3][ar + 64] = f2tf32(a1.w);
        uint4 pb0 = make_uint4(f2tf32(b0.x), f2tf32(b0.y), f2tf32(b0.z), f2tf32(b0.w));
        uint4 pb1 = make_uint4(f2tf32(b1.x), f2tf32(b1.y), f2tf32(b1.z), f2tf32(b1.w));
        *(uint4*)&Bs[nb][br][bc] = pb0;
        *(uint4*)&Bs[nb][br + 8][bc] = pb1;
        __syncthreads();
        buf = nb;
    }
    compute_slab16(&As[buf][0][0], &Bs[buf][0][0], acc, wm, wn, g, tig);
}

// generic epilogue: store acc (optionally scaled) to C (ldc)
__device__ __forceinline__ void store_tile(float* __restrict__ C, int ldc, float scale,
                                           const float (&acc)[4][4][4])
{
    const int tid = threadIdx.x;
    const int lane = tid & 31, wid = tid >> 5;
    const int g = lane >> 2, tig = lane & 3;
    const int wm = (wid >> 2) * 64, wn = (wid & 3) * 32;
    const int crow = blockIdx.y * 128, ccol = blockIdx.x * 128;
#pragma unroll
    for (int mi = 0; mi < 4; mi++) {
        const int r = crow + wm + mi * 16 + g;
#pragma unroll
        for (int ni = 0; ni < 4; ni++) {
            const int c = ccol + wn + ni * 8 + 2 * tig;
            *(float2*)&C[(size_t)r * ldc + c] =
                make_float2(acc[mi][ni][0] * scale, acc[mi][ni][1] * scale);
            *(float2*)&C[(size_t)(r + 8) * ldc + c] =
                make_float2(acc[mi][ni][2] * scale, acc[mi][ni][3] * scale);
        }
    }
}

// ---------------- splat parameter precompute (tiny) ----------------
__global__ void prep_kernel(const float* __restrict__ pos_in, const float* __restrict__ dir_in,
                            const float* __restrict__ lsc, const float* __restrict__ lam,
                            const float* __restrict__ dstr, const float* __restrict__ gstr)
{
    int i = threadIdx.x;  // 0..127 = h*NS+n
    const float eps = 1e-12f;
    const float* p  = pos_in + i * Dn;
    const float* dr = dir_in + i * Dn;
    float np = 0.f, nd = 0.f;
    for (int d = 0; d < Dn; d++) { np += p[d] * p[d]; nd += dr[d] * dr[d]; }
    np = sqrtf(np) + eps; nd = sqrtf(nd) + eps;
    const float sp = sqrtf((float)Dn) * 0.3f;
    float psq = 0.f, pd = 0.f;
    for (int d = 0; d < Dn; d++) {
        float pv = p[d] / np * sp;
        float dv = dr[d] / nd;
        g_pos[i * Dn + d] = pv;
        g_dir[i * Dn + d] = dv;
        psq += pv * pv; pd += pv * dv;
    }
    g_possq[i] = psq;
    g_posdot[i] = pd;
    float sc = expf(lsc[i]);
    sc = fminf(fmaxf(sc, 0.3f), 1.2f);
    g_i2s2[i] = 0.5f / (sc * sc);
    __syncthreads();
    if (i < NHn) {
        float mx = -1e30f;
        for (int n = 0; n < NSn; n++) mx = fmaxf(mx, lam[i * NSn + n]);
        float e[NSn], s = 0.f;
        for (int n = 0; n < NSn; n++) { e[n] = expf(lam[i * NSn + n] - mx); s += e[n]; }
        for (int n = 0; n < NSn; n++) g_amp[i * NSn + n] = e[n] / s;
    }
    if (i == 0) {
        g_scal[0] = 1.f / (1.f + expf(-dstr[0]));
        float gs  = 1.f / (1.f + expf(-gstr[0]));
        g_scal[1] = fminf(0.05f, gs * 0.1f);
    }
}

// ---------------- big GEMMs (tf32 tensor) ----------------
__global__ void __launch_bounds__(256, 2) gemm_qkv(const float* __restrict__ X,
                                                   const float* __restrict__ Wq,
                                                   const float* __restrict__ Wk,
                                                   const float* __restrict__ Wv)
{
    const int z = blockIdx.z;
    const float* W = (z == 0) ? Wq : (z == 1) ? Wk : Wv;
    float* C = (z == 0) ? g_Q : (z == 1) ? g_K : g_V;
    float acc[4][4][4] = {};
    mma_nn_loop(X, HIDn, W, HIDn, HIDn, acc);
    store_tile(C, HIDn, 1.0f, acc);
}

__global__ void __launch_bounds__(256, 2) gemm_out(const float* __restrict__ Wo,
                                                   float* __restrict__ out)
{
    float acc[4][4][4] = {};
    mma_nn_loop(g_CTX, HIDn, Wo, HIDn, HIDn, acc);
    store_tile(out, HIDn, 1.0f, acc);
}

// ---------------- splat affinities: one warp per token; z selects Q/K ----------------
__global__ void __launch_bounds__(256) affinity_kernel()
{
    const int which = blockIdx.z;
    const float* T = (which == 0) ? g_Q : g_K;
    float* out = (which == 0) ? g_qa : g_ka;
    const int lane = threadIdx.x & 31;
    const int token = blockIdx.x * 8 + (threadIdx.x >> 5);
    if (token >= BHn * Sn) return;
    const int s = token & (Sn - 1);
    const int bh = token >> 10;
    const int h = bh & (NHn - 1), b = bh >> 4;
    const float* x = T + (size_t)(b * Sn + s) * HIDn + h * Dn;
    float x0 = x[lane], x1 = x[lane + 32], x2 = x[lane + 64], x3 = x[lane + 96];
    float tsq = warp_sum(x0 * x0 + x1 * x1 + x2 * x2 + x3 * x3);
    float ds = g_scal[0];
#pragma unroll
    for (int n = 0; n < NSn; n++) {
        const int hn = h * NSn + n;
        const float* pp = g_pos + hn * Dn;
        const float* dd = g_dir + hn * Dn;
        float tp = warp_sum(x0 * pp[lane] + x1 * pp[lane + 32] + x2 * pp[lane + 64] + x3 * pp[lane + 96]);
        float xd = warp_sum(x0 * dd[lane] + x1 * dd[lane + 32] + x2 * dd[lane + 64] + x3 * dd[lane + 96]);
        float dist2 = fmaxf(tsq - 2.f * tp + g_possq[hn], 0.f);
        float proj  = xd - g_posdot[hn];
        float perp2 = fmaxf(dist2 - proj * proj, 0.f);
        float i2 = g_i2s2[hn];
        float aff = (1.f - ds) * expf(-dist2 * i2) + ds * expf(-perp2 * i2);
        if (lane == 0) out[(size_t)token * NSn + n] = aff;
    }
}

// ---------------- M[n,:] = sum_s ka[s,n] * v[s,:], s_k[n] = sum_s ka[s,n] ----------------
__global__ void __launch_bounds__(128) ksum_kernel()
{
    const int idx = blockIdx.x;            // bh*NS+n, 0..255
    const int n = idx & 7, bh = idx >> 3;
    const int h = bh & 15, b = bh >> 4;
    const int d = threadIdx.x;
    const float* vb = g_V + (size_t)b * Sn * HIDn + h * Dn + d;
    const float* kb = g_ka + (size_t)bh * Sn * NSn + n;
    float acc = 0.f, ska = 0.f;
    for (int s = 0; s < Sn; s += 4) {
        float k0 = kb[(size_t)(s + 0) * NSn];
        float k1 = kb[(size_t)(s + 1) * NSn];
        float k2 = kb[(size_t)(s + 2) * NSn];
        float k3 = kb[(size_t)(s + 3) * NSn];
        acc += k0 * vb[(size_t)(s + 0) * HIDn];
        acc += k1 * vb[(size_t)(s + 1) * HIDn];
        acc += k2 * vb[(size_t)(s + 2) * HIDn];
        acc += k3 * vb[(size_t)(s + 3) * HIDn];
        ska += k0 + k1 + k2 + k3;
    }
    g_M[(size_t)idx * Dn + d] = acc;
    if (d == 0) g_sk[idx] = ska;
}

// ============ fused flash attention: scores + softmax + PV + GSA blend ============
// grid (Sn/128, BHn), 256 threads. Dynamic smem layout (uint32 words):
//   Qs [128][136] @0        (17408)   tf32, k(d)-major
//   Ps [128][136] @17408    (17408)   tf32, k(kcol)-major
//   KV [2][16][136] @34816  (4352)    tf32 slab double-buffer
//   redm [4][128] @39168    (512)     fp32 row-max partials
//   reds [4][128] @39680    (512)     fp32 row-sum partials
//   Msm [8][128] @40192     (1024)
//   ampsm[8] @41216, sksm[8] @41224   (16)
#define FLASH_SMEM_WORDS 41232
#define FLASH_SMEM_BYTES (FLASH_SMEM_WORDS * 4)

__global__ void __launch_bounds__(256) flash_attn_kernel()
{
    extern __shared__ uint32_t smx[];
    uint32_t* Qs = smx;
    uint32_t* Ps = smx + 17408;
    uint32_t* KV = smx + 34816;
    float* redm  = (float*)(smx + 39168);
    float* reds  = (float*)(smx + 39680);
    float* Msm   = (float*)(smx + 40192);
    float* ampsm = (float*)(smx + 41216);
    float* sksm  = ampsm + 8;

    const int bh = blockIdx.y;
    const int b = bh >> 4, h = bh & 15;
    const int qrow0 = blockIdx.x * 128;
    const int tid = threadIdx.x;
    const int lane = tid & 31, wid = tid >> 5;
    const int g = lane >> 2, tig = lane & 3;
    const int wm = (wid >> 2) * 64, wn = (wid & 3) * 32;
    const int wnidx = wid & 3;

    // GSA constants for epilogue
    for (int i = tid; i < NSn * Dn; i += 256) Msm[i] = g_M[(size_t)bh * NSn * Dn + i];
    if (tid < NSn) { ampsm[tid] = g_amp[h * NSn + tid]; sksm[tid] = g_sk[bh * NSn + tid]; }

    // load Q tile -> Qs[d][row] (tf32)
    const float* Qg = g_Q + (size_t)(b * Sn + qrow0) * HIDn + h * Dn;
    {
        const int ar = tid >> 1, dc4 = (tid & 1) * 4;
#pragma unroll
        for (int dch = 0; dch < Dn; dch += 8) {
            float4 q = *(const float4*)(Qg + (size_t)ar * HIDn + dch + dc4);
            const int d = dch + dc4;
            Qs[(d + 0) * 136 + ar] = f2tf32(q.x);
            Qs[(d + 1) * 136 + ar] = f2tf32(q.y);
            Qs[(d + 2) * 136 + ar] = f2tf32(q.z);
            Qs[(d + 3) * 136 + ar] = f2tf32(q.w);
        }
    }
    __syncthreads();

    float m_i[4][2], l_i[4][2];
#pragma unroll
    for (int mi = 0; mi < 4; mi++) {
        m_i[mi][0] = m_i[mi][1] = -1e30f;
        l_i[mi][0] = l_i[mi][1] = 0.f;
    }
    float o[4][4][4] = {};

    const float SCALE = 0.0883883476483184f;   // 1/sqrt(128)
    const int kcolL = tid >> 1, dbase = (tid & 1) * 4;   // K-slab loader mapping
    const int vr = tid >> 5,  vc4 = (tid & 31) * 4;      // V-slab loader mapping

    for (int kt = 0; kt < Sn / 128; kt++) {
        const float* Kg = g_K + (size_t)(b * Sn + kt * 128) * HIDn + h * Dn;
        const float* Vg = g_V + (size_t)(b * Sn + kt * 128) * HIDn + h * Dn;

        // ---- S = Q @ K^T over d (8 slabs of 16) ----
        float s[4][4][4] = {};
        {
            float4 k0 = *(const float4*)(Kg + (size_t)kcolL * HIDn + dbase);
            float4 k1 = *(const float4*)(Kg + (size_t)kcolL * HIDn + dbase + 8);
            stA_slab(KV, dbase, kcolL, k0, k1);
        }
        __syncthreads();
        int buf = 0;
        for (int slab = 1; slab <= 8; slab++) {
            float4 n0, n1;
            if (slab < 8) {
                n0 = *(const float4*)(Kg + (size_t)kcolL * HIDn + slab * 16 + dbase);
                n1 = *(const float4*)(Kg + (size_t)kcolL * HIDn + slab * 16 + dbase + 8);
            }
            compute_slab16(Qs + (slab - 1) * 16 * 136, KV + buf * 2176, s, wm, wn, g, tig);
            if (slab < 8) stA_slab(KV + (buf ^ 1) * 2176, dbase, kcolL, n0, n1);
            __syncthreads();
            buf ^= 1;
        }

        // ---- online softmax: scale, row max (intra-warp + cross-warp) ----
        float alpha[4][2];
#pragma unroll
        for (int mi = 0; mi < 4; mi++)
#pragma unroll
            for (int hf = 0; hf < 2; hf++) {
                float pm = -1e30f;
#pragma unroll
                for (int ni = 0; ni < 4; ni++) {
                    s[mi][ni][hf * 2 + 0] *= SCALE;
                    s[mi][ni][hf * 2 + 1] *= SCALE;
                    pm = fmaxf(pm, fmaxf(s[mi][ni][hf * 2], s[mi][ni][hf * 2 + 1]));
                }
                pm = fmaxf(pm, __shfl_xor_sync(0xffffffffu, pm, 1));
                pm = fmaxf(pm, __shfl_xor_sync(0xffffffffu, pm, 2));
                if (tig == 0) redm[wnidx * 128 + wm + mi * 16 + g + 8 * hf] = pm;
            }
        __syncthreads();
#pragma unroll
        for (int mi = 0; mi < 4; mi++)
#pragma unroll
            for (int hf = 0; hf < 2; hf++) {
                const int row = wm + mi * 16 + g + 8 * hf;
                float rm = fmaxf(fmaxf(redm[row], redm[128 + row]),
                                 fmaxf(redm[256 + row], redm[384 + row]));
                float mn = fmaxf(m_i[mi][hf], rm);
                alpha[mi][hf] = __expf(m_i[mi][hf] - mn);
                m_i[mi][hf] = mn;
            }

        // ---- P = exp(S - m), store to Ps (A-layout), partial row sums, rescale O ----
#pragma unroll
        for (int mi = 0; mi < 4; mi++)
#pragma unroll
            for (int hf = 0; hf < 2; hf++) {
                const int row = wm + mi * 16 + g + 8 * hf;
                float ps = 0.f;
#pragma unroll
                for (int ni = 0; ni < 4; ni++) {
                    const int c = wn + ni * 8 + 2 * tig;
                    float p0 = __expf(s[mi][ni][hf * 2 + 0] - m_i[mi][hf]);
                    float p1 = __expf(s[mi][ni][hf * 2 + 1] - m_i[mi][hf]);
                    ps += p0 + p1;
                    Ps[(c + 0) * 136 + row] = f2tf32(p0);
                    Ps[(c + 1) * 136 + row] = f2tf32(p1);
                    o[mi][ni][hf * 2 + 0] *= alpha[mi][hf];
                    o[mi][ni][hf * 2 + 1] *= alpha[mi][hf];
                }
                ps += __shfl_xor_sync(0xffffffffu, ps, 1);
                ps += __shfl_xor_sync(0xffffffffu, ps, 2);
                if (tig == 0) reds[wnidx * 128 + row] = ps;
            }
        __syncthreads();
#pragma unroll
        for (int mi = 0; mi < 4; mi++)
#pragma unroll
            for (int hf = 0; hf < 2; hf++) {
                const int row = wm + mi * 16 + g + 8 * hf;
                float rs = reds[row] + reds[128 + row] + reds[256 + row] + reds[384 + row];
                l_i[mi][hf] = l_i[mi][hf] * alpha[mi][hf] + rs;
            }

        // ---- O += P @ V over kcol (8 slabs of 16) ----
        {
            float4 v0 = *(const float4*)(Vg + (size_t)vr * HIDn + vc4);
            float4 v1 = *(const float4*)(Vg + (size_t)(vr + 8) * HIDn + vc4);
            stB_slab(KV, vr, vc4, v0, v1);
        }
        __syncthreads();
        buf = 0;
        for (int slab = 1; slab <= 8; slab++) {
            float4 n0, n1;
            if (slab < 8) {
                n0 = *(const float4*)(Vg + (size_t)(slab * 16 + vr) * HIDn + vc4);
                n1 = *(const float4*)(Vg + (size_t)(slab * 16 + vr + 8) * HIDn + vc4);
            }
            compute_slab16(Ps + (slab - 1) * 16 * 136, KV + buf * 2176, o, wm, wn, g, tig);
            if (slab < 8) stB_slab(KV + (buf ^ 1) * 2176, vr, vc4, n0, n1);
            __syncthreads();
            buf ^= 1;
        }
    }

    // ---- normalize + GSA blend epilogue ----
    const float blend = g_scal[1];
    const float ob = 1.f - blend;
    float* Cb = g_CTX + (size_t)b * Sn * HIDn + h * Dn;
#pragma unroll
    for (int mi = 0; mi < 4; mi++)
#pragma unroll
        for (int hf = 0; hf < 2; hf++) {
            const int r = qrow0 + wm + mi * 16 + g + 8 * hf;
            const float invl = 1.f / l_i[mi][hf];
            const float4 qa0 = *(const float4*)&g_qa[((size_t)bh * Sn + r) * NSn];
            const float4 qa1 = *(const float4*)&g_qa[((size_t)bh * Sn + r) * NSn + 4];
            float wq[8];
            wq[0] = qa0.x * ampsm[0]; wq[1] = qa0.y * ampsm[1];
            wq[2] = qa0.z * ampsm[2]; wq[3] = qa0.w * ampsm[3];
            wq[4] = qa1.x * ampsm[4]; wq[5] = qa1.y * ampsm[5];
            wq[6] = qa1.z * ampsm[6]; wq[7] = qa1.w * ampsm[7];
            float den = 1e-8f;
#pragma unroll
            for (int n = 0; n < 8; n++) den += wq[n] * sksm[n];
            const float invden = 1.f / den;
#pragma unroll
            for (int ni = 0; ni < 4; ni++) {
                const int c = wn + ni * 8 + 2 * tig;
                float dg0 = 0.f, dg1 = 0.f;
#pragma unroll
                for (int n = 0; n < 8; n++) {
                    dg0 += wq[n] * Msm[n * 128 + c];
                    dg1 += wq[n] * Msm[n * 128 + c + 1];
                }
                const float a0 = o[mi][ni][hf * 2 + 0] * invl;
                const float a1 = o[mi][ni][hf * 2 + 1] * invl;
                *(float2*)&Cb[(size_t)r * HIDn + c] =
                    make_float2(ob * a0 + blend * dg0 * invden,
                                ob * a1 + blend * dg1 * invden);
            }
        }
}

// ---------------- launch ----------------
extern "C" void kernel_launch(void* const* d_in, const int* in_sizes, int n_in,
                              void* d_out, int out_size)
{
    (void)in_sizes; (void)n_in; (void)out_size;
    const float* hs   = (const float*)d_in[0];
    const float* Wq   = (const float*)d_in[1];
    const float* Wk   = (const float*)d_in[2];
    const float* Wv   = (const float*)d_in[3];
    const float* Wo   = (const float*)d_in[4];
    const float* spos = (const float*)d_in[5];
    const float* sdir = (const float*)d_in[6];
    const float* lsc  = (const float*)d_in[7];
    const float* lam  = (const float*)d_in[8];
    const float* dstr = (const float*)d_in[9];
    const float* gstr = (const float*)d_in[10];
    float* out = (float*)d_out;

    cudaFuncSetAttribute(flash_attn_kernel,
                         cudaFuncAttributeMaxDynamicSharedMemorySize, FLASH_SMEM_BYTES);

    prep_kernel<<<1, 128>>>(spos, sdir, lsc, lam, dstr, gstr);
    gemm_qkv<<<dim3(16, 16, 3), 256>>>(hs, Wq, Wk, Wv);
    affinity_kernel<<<dim3(4096, 1, 2), 256>>>();
    ksum_kernel<<<256, 128>>>();
    flash_attn_kernel<<<dim3(Sn / 128, BHn), 256, FLASH_SMEM_BYTES>>>();
    gemm_out<<<dim3(16, 16), 256>>>(Wo, out);
}

// round 12
// speedup vs baseline: 2.6881x; 1.0431x over previous
#include <cuda_runtime.h>
#include <math.h>
#include <stdint.h>

#define Bn   2
#define Sn   1024
#define HIDn 2048
#define NHn  16
#define NSn  8
#define Dn   128
#define BSn  (Bn*Sn)    // 2048
#define BHn  (Bn*NHn)   // 32
#define NCHUNK 8        // s-chunks per bh in ksum

// ---------------- scratch (device globals; no runtime alloc) ----------------
__device__ float g_Q[BSn*HIDn];
__device__ float g_K[BSn*HIDn];
__device__ float g_V[BSn*HIDn];
__device__ float g_CTX[BSn*HIDn];
__device__ float g_qa[BHn*Sn*NSn];
__device__ float g_ka[BHn*Sn*NSn];
__device__ float g_Mpart[BHn*NCHUNK*NSn*Dn];   // per-chunk partial M
__device__ float g_skpart[BHn*NCHUNK*NSn];     // per-chunk partial s_k
__device__ float g_pos[NHn*NSn*Dn];
__device__ float g_dir[NHn*NSn*Dn];
__device__ float g_possq[NHn*NSn];
__device__ float g_posdot[NHn*NSn];
__device__ float g_i2s2[NHn*NSn];
__device__ float g_amp[NHn*NSn];
__device__ float g_scal[2];                    // [0]=dir_strength sigmoid, [1]=blend

__device__ __forceinline__ float warp_sum(float v) {
#pragma unroll
    for (int o = 16; o > 0; o >>= 1) v += __shfl_xor_sync(0xffffffffu, v, o);
    return v;
}

// ---------------- tf32 mma primitives ----------------
__device__ __forceinline__ uint32_t f2tf32(float x) {
    uint32_t r;
    asm("cvt.rna.tf32.f32 %0, %1;" : "=r"(r) : "f"(x));
    return r;
}

__device__ __forceinline__ void mma8(float* c, const uint32_t* a, const uint32_t* b) {
    asm volatile(
        "mma.sync.aligned.m16n8k8.row.col.f32.tf32.tf32.f32 "
        "{%0,%1,%2,%3}, {%4,%5,%6,%7}, {%8,%9}, {%0,%1,%2,%3};"
        : "+f"(c[0]), "+f"(c[1]), "+f"(c[2]), "+f"(c[3])
        : "r"(a[0]), "r"(a[1]), "r"(a[2]), "r"(a[3]), "r"(b[0]), "r"(b[1]));
}

// Compute 32 mma ops per warp over a BK=16 slab. As/Bs stride 136 words.
__device__ __forceinline__ void compute_slab16(const uint32_t* __restrict__ As,
                                               const uint32_t* __restrict__ Bs,
                                               float (&acc)[4][4][4],
                                               int wm, int wn, int g, int tig)
{
#pragma unroll
    for (int ks = 0; ks < 16; ks += 8) {
        uint32_t a[4][4], b[4][2];
#pragma unroll
        for (int mi = 0; mi < 4; mi++) {
            const int r = wm + mi * 16 + g;
            a[mi][0] = As[(ks + tig) * 136 + r];
            a[mi][1] = As[(ks + tig) * 136 + r + 8];
            a[mi][2] = As[(ks + tig + 4) * 136 + r];
            a[mi][3] = As[(ks + tig + 4) * 136 + r + 8];
        }
#pragma unroll
        for (int ni = 0; ni < 4; ni++) {
            const int c = wn + ni * 8 + g;
            b[ni][0] = Bs[(ks + tig) * 136 + c];
            b[ni][1] = Bs[(ks + tig + 4) * 136 + c];
        }
#pragma unroll
        for (int mi = 0; mi < 4; mi++)
#pragma unroll
            for (int ni = 0; ni < 4; ni++)
                mma8(acc[mi][ni], a[mi], b[ni]);
    }
}

// scatter 2 float4 (k-major A layout): S[k][col], k = dbase..dbase+3 and +8..+11
__device__ __forceinline__ void stA_slab(uint32_t* S, int dbase, int col, float4 q0, float4 q1) {
    S[(dbase + 0) * 136 + col] = f2tf32(q0.x);
    S[(dbase + 1) * 136 + col] = f2tf32(q0.y);
    S[(dbase + 2) * 136 + col] = f2tf32(q0.z);
    S[(dbase + 3) * 136 + col] = f2tf32(q0.w);
    S[(dbase + 8) * 136 + col] = f2tf32(q1.x);
    S[(dbase + 9) * 136 + col] = f2tf32(q1.y);
    S[(dbase + 10) * 136 + col] = f2tf32(q1.z);
    S[(dbase + 11) * 136 + col] = f2tf32(q1.w);
}

// direct 2 uint4 (n-major B layout): S[r][c4..c4+3], rows r and r+8
__device__ __forceinline__ void stB_slab(uint32_t* S, int r, int c4, float4 v0, float4 v1) {
    uint4 p0 = make_uint4(f2tf32(v0.x), f2tf32(v0.y), f2tf32(v0.z), f2tf32(v0.w));
    uint4 p1 = make_uint4(f2tf32(v1.x), f2tf32(v1.y), f2tf32(v1.z), f2tf32(v1.w));
    *(uint4*)&S[r * 136 + c4] = p0;
    *(uint4*)&S[(r + 8) * 136 + c4] = p1;
}

// ---- NN mainloop (for 2048^3 GEMMs): 128x128 tile, BK=16, dbl-buffered ----
__device__ __forceinline__ void mma_nn_loop(const float* __restrict__ Ag, int lda,
                                            const float* __restrict__ Bg, int ldb,
                                            int K, float (&acc)[4][4][4])
{
    __shared__ uint32_t As[2][16][136];
    __shared__ uint32_t Bs[2][16][136];
    const int tid = threadIdx.x;
    const int lane = tid & 31, wid = tid >> 5;
    const int g = lane >> 2, tig = lane & 3;
    const int wm = (wid >> 2) * 64, wn = (wid & 3) * 32;
    const int crow = blockIdx.y * 128, ccol = blockIdx.x * 128;
    const int ar = tid >> 2,  ak = (tid & 3) * 4;
    const int br = tid >> 5,  bc = (tid & 31) * 4;
    const float* A0 = Ag + (size_t)(crow + ar) * lda + ak;
    const float* A1 = Ag + (size_t)(crow + ar + 64) * lda + ak;
    const float* B0 = Bg + (size_t)br * ldb + ccol + bc;
    const float* B1 = Bg + (size_t)(br + 8) * ldb + ccol + bc;

    {
        float4 a0 = *(const float4*)A0;
        float4 a1 = *(const float4*)A1;
        float4 b0 = *(const float4*)B0;
        float4 b1 = *(const float4*)B1;
        As[0][ak + 0][ar] = f2tf32(a0.x); As[0][ak + 1][ar] = f2tf32(a0.y);
        As[0][ak + 2][ar] = f2tf32(a0.z); As[0][ak + 3][ar] = f2tf32(a0.w);
        As[0][ak + 0][ar + 64] = f2tf32(a1.x); As[0][ak + 1][ar + 64] = f2tf32(a1.y);
        As[0][ak + 2][ar + 64] = f2tf32(a1.z); As[0][ak + 3][ar + 64] = f2tf32(a1.w);
        uint4 pb0 = make_uint4(f2tf32(b0.x), f2tf32(b0.y), f2tf32(b0.z), f2tf32(b0.w));
        uint4 pb1 = make_uint4(f2tf32(b1.x), f2tf32(b1.y), f2tf32(b1.z), f2tf32(b1.w));
        *(uint4*)&Bs[0][br][bc] = pb0;
        *(uint4*)&Bs[0][br + 8][bc] = pb1;
    }
    __syncthreads();

    int buf = 0;
    for (int k0 = 16; k0 < K; k0 += 16) {
        float4 a0 = *(const float4*)(A0 + k0);
        float4 a1 = *(const float4*)(A1 + k0);
        float4 b0 = *(const float4*)(B0 + (size_t)k0 * ldb);
        float4 b1 = *(const float4*)(B1 + (size_t)k0 * ldb);

        compute_slab16(&As[buf][0][0], &Bs[buf][0][0], acc, wm, wn, g, tig);

        const int nb = buf ^ 1;
        As[nb][ak + 0][ar] = f2tf32(a0.x); As[nb][ak + 1][ar] = f2tf32(a0.y);
        As[nb][ak + 2][ar] = f2tf32(a0.z); As[nb][ak + 3][ar] = f2tf32(a0.w);
        As[nb][ak + 0][ar + 64] = f2tf32(a1.x); As[nb][ak + 1][ar + 64] = f2tf32(a1.y);
        As[nb][ak + 2][ar + 64] = f2tf32(a1.z); As[nb][ak + 3][ar + 64] = f2tf32(a1.w);
        uint4 pb0 = make_uint4(f2tf32(b0.x), f2tf32(b0.y), f2tf32(b0.z), f2tf32(b0.w));
        uint4 pb1 = make_uint4(f2tf32(b1.x), f2tf32(b1.y), f2tf32(b1.z), f2tf32(b1.w));
        *(uint4*)&Bs[nb][br][bc] = pb0;
        *(uint4*)&Bs[nb][br + 8][bc] = pb1;
        __syncthreads();
        buf = nb;
    }
    compute_slab16(&As[buf][0][0], &Bs[buf][0][0], acc, wm, wn, g, tig);
}

// generic epilogue: store acc (optionally scaled) to C (ldc)
__device__ __forceinline__ void store_tile(float* __restrict__ C, int ldc, float scale,
                                           const float (&acc)[4][4][4])
{
    const int tid = threadIdx.x;
    const int lane = tid & 31, wid = tid >> 5;
    const int g = lane >> 2, tig = lane & 3;
    const int wm = (wid >> 2) * 64, wn = (wid & 3) * 32;
    const int crow = blockIdx.y * 128, ccol = blockIdx.x * 128;
#pragma unroll
    for (int mi = 0; mi < 4; mi++) {
        const int r = crow + wm + mi * 16 + g;
#pragma unroll
        for (int ni = 0; ni < 4; ni++) {
            const int c = ccol + wn + ni * 8 + 2 * tig;
            *(float2*)&C[(size_t)r * ldc + c] =
                make_float2(acc[mi][ni][0] * scale, acc[mi][ni][1] * scale);
            *(float2*)&C[(size_t)(r + 8) * ldc + c] =
                make_float2(acc[mi][ni][2] * scale, acc[mi][ni][3] * scale);
        }
    }
}

// ---------------- splat parameter precompute (tiny) ----------------
__global__ void prep_kernel(const float* __restrict__ pos_in, const float* __restrict__ dir_in,
                            const float* __restrict__ lsc, const float* __restrict__ lam,
                            const float* __restrict__ dstr, const float* __restrict__ gstr)
{
    int i = threadIdx.x;  // 0..127 = h*NS+n
    const float eps = 1e-12f;
    const float* p  = pos_in + i * Dn;
    const float* dr = dir_in + i * Dn;
    float np = 0.f, nd = 0.f;
    for (int d = 0; d < Dn; d++) { np += p[d] * p[d]; nd += dr[d] * dr[d]; }
    np = sqrtf(np) + eps; nd = sqrtf(nd) + eps;
    const float sp = sqrtf((float)Dn) * 0.3f;
    float psq = 0.f, pd = 0.f;
    for (int d = 0; d < Dn; d++) {
        float pv = p[d] / np * sp;
        float dv = dr[d] / nd;
        g_pos[i * Dn + d] = pv;
        g_dir[i * Dn + d] = dv;
        psq += pv * pv; pd += pv * dv;
    }
    g_possq[i] = psq;
    g_posdot[i] = pd;
    float sc = expf(lsc[i]);
    sc = fminf(fmaxf(sc, 0.3f), 1.2f);
    g_i2s2[i] = 0.5f / (sc * sc);
    __syncthreads();
    if (i < NHn) {
        float mx = -1e30f;
        for (int n = 0; n < NSn; n++) mx = fmaxf(mx, lam[i * NSn + n]);
        float e[NSn], s = 0.f;
        for (int n = 0; n < NSn; n++) { e[n] = expf(lam[i * NSn + n] - mx); s += e[n]; }
        for (int n = 0; n < NSn; n++) g_amp[i * NSn + n] = e[n] / s;
    }
    if (i == 0) {
        g_scal[0] = 1.f / (1.f + expf(-dstr[0]));
        float gs  = 1.f / (1.f + expf(-gstr[0]));
        g_scal[1] = fminf(0.05f, gs * 0.1f);
    }
}

// ---------------- big GEMMs (tf32 tensor) ----------------
__global__ void __launch_bounds__(256, 2) gemm_qkv(const float* __restrict__ X,
                                                   const float* __restrict__ Wq,
                                                   const float* __restrict__ Wk,
                                                   const float* __restrict__ Wv)
{
    const int z = blockIdx.z;
    const float* W = (z == 0) ? Wq : (z == 1) ? Wk : Wv;
    float* C = (z == 0) ? g_Q : (z == 1) ? g_K : g_V;
    float acc[4][4][4] = {};
    mma_nn_loop(X, HIDn, W, HIDn, HIDn, acc);
    store_tile(C, HIDn, 1.0f, acc);
}

__global__ void __launch_bounds__(256, 2) gemm_out(const float* __restrict__ Wo,
                                                   float* __restrict__ out)
{
    float acc[4][4][4] = {};
    mma_nn_loop(g_CTX, HIDn, Wo, HIDn, HIDn, acc);
    store_tile(out, HIDn, 1.0f, acc);
}

// ---------------- splat affinities: one warp per token; z selects Q/K ----------------
__global__ void __launch_bounds__(256) affinity_kernel()
{
    const int which = blockIdx.z;
    const float* T = (which == 0) ? g_Q : g_K;
    float* out = (which == 0) ? g_qa : g_ka;
    const int lane = threadIdx.x & 31;
    const int token = blockIdx.x * 8 + (threadIdx.x >> 5);
    if (token >= BHn * Sn) return;
    const int s = token & (Sn - 1);
    const int bh = token >> 10;
    const int h = bh & (NHn - 1), b = bh >> 4;
    const float* x = T + (size_t)(b * Sn + s) * HIDn + h * Dn;
    float x0 = x[lane], x1 = x[lane + 32], x2 = x[lane + 64], x3 = x[lane + 96];
    float tsq = warp_sum(x0 * x0 + x1 * x1 + x2 * x2 + x3 * x3);
    float ds = g_scal[0];
#pragma unroll
    for (int n = 0; n < NSn; n++) {
        const int hn = h * NSn + n;
        const float* pp = g_pos + hn * Dn;
        const float* dd = g_dir + hn * Dn;
        float tp = warp_sum(x0 * pp[lane] + x1 * pp[lane + 32] + x2 * pp[lane + 64] + x3 * pp[lane + 96]);
        float xd = warp_sum(x0 * dd[lane] + x1 * dd[lane + 32] + x2 * dd[lane + 64] + x3 * dd[lane + 96]);
        float dist2 = fmaxf(tsq - 2.f * tp + g_possq[hn], 0.f);
        float proj  = xd - g_posdot[hn];
        float perp2 = fmaxf(dist2 - proj * proj, 0.f);
        float i2 = g_i2s2[hn];
        float aff = (1.f - ds) * expf(-dist2 * i2) + ds * expf(-perp2 * i2);
        if (lane == 0) out[(size_t)token * NSn + n] = aff;
    }
}

// ---- ksum v2: chunked outer product. grid 256 = (bh, chunk); V read exactly once. ----
// Block (bh, c): partial M over s in [c*128,(c+1)*128): Mpart[n][d] = sum ka[s][n]*v[s][d]
__global__ void __launch_bounds__(128) ksum_kernel()
{
    __shared__ float kas[128 * NSn];            // ka slice, [s][n]
    const int blk = blockIdx.x;                 // bh*NCHUNK + chunk
    const int chunk = blk & (NCHUNK - 1), bh = blk >> 3;
    const int h = bh & 15, b = bh >> 4;
    const int d = threadIdx.x;
    const int s0 = chunk * 128;

    // coalesced copy of 128x8 ka slice
    const float* kab = g_ka + ((size_t)bh * Sn + s0) * NSn;
    for (int i = d; i < 128 * NSn; i += 128) kas[i] = kab[i];
    __syncthreads();

    const float* vb = g_V + (size_t)(b * Sn + s0) * HIDn + h * Dn + d;
    float acc[NSn] = {};
#pragma unroll 4
    for (int s = 0; s < 128; s++) {
        const float v = vb[(size_t)s * HIDn];
        const float* kr = &kas[s * NSn];
#pragma unroll
        for (int n = 0; n < NSn; n++) acc[n] += kr[n] * v;
    }
    float* mp = g_Mpart + (size_t)blk * NSn * Dn;
#pragma unroll
    for (int n = 0; n < NSn; n++) mp[n * Dn + d] = acc[n];

    // s_k partials: thread n (<8) sums its column
    if (d < NSn) {
        float ska = 0.f;
#pragma unroll 4
        for (int s = 0; s < 128; s++) ska += kas[s * NSn + d];
        g_skpart[blk * NSn + d] = ska;
    }
}

// ============ fused flash attention: scores + softmax + PV + GSA blend ============
// grid (Sn/128, BHn), 256 threads. Dynamic smem layout (uint32 words):
//   Qs [128][136] @0        (17408)   tf32, k(d)-major
//   Ps [128][136] @17408    (17408)   tf32, k(kcol)-major
//   KV [2][16][136] @34816  (4352)    tf32 slab double-buffer
//   redm [4][128] @39168    (512)     fp32 row-max partials
//   reds [4][128] @39680    (512)     fp32 row-sum partials
//   Msm [8][128] @40192     (1024)
//   ampsm[8] @41216, sksm[8] @41224   (16)
#define FLASH_SMEM_WORDS 41232
#define FLASH_SMEM_BYTES (FLASH_SMEM_WORDS * 4)

__global__ void __launch_bounds__(256) flash_attn_kernel()
{
    extern __shared__ uint32_t smx[];
    uint32_t* Qs = smx;
    uint32_t* Ps = smx + 17408;
    uint32_t* KV = smx + 34816;
    float* redm  = (float*)(smx + 39168);
    float* reds  = (float*)(smx + 39680);
    float* Msm   = (float*)(smx + 40192);
    float* ampsm = (float*)(smx + 41216);
    float* sksm  = ampsm + 8;

    const int bh = blockIdx.y;
    const int b = bh >> 4, h = bh & 15;
    const int qrow0 = blockIdx.x * 128;
    const int tid = threadIdx.x;
    const int lane = tid & 31, wid = tid >> 5;
    const int g = lane >> 2, tig = lane & 3;
    const int wm = (wid >> 2) * 64, wn = (wid & 3) * 32;
    const int wnidx = wid & 3;

    // GSA constants: sum ksum chunk partials
    for (int i = tid; i < NSn * Dn; i += 256) {
        float acc = 0.f;
#pragma unroll
        for (int c = 0; c < NCHUNK; c++)
            acc += g_Mpart[((size_t)(bh * NCHUNK + c)) * NSn * Dn + i];
        Msm[i] = acc;
    }
    if (tid < NSn) {
        float acc = 0.f;
#pragma unroll
        for (int c = 0; c < NCHUNK; c++)
            acc += g_skpart[(bh * NCHUNK + c) * NSn + tid];
        sksm[tid] = acc;
        ampsm[tid] = g_amp[h * NSn + tid];
    }

    // load Q tile -> Qs[d][row] (tf32)
    const float* Qg = g_Q + (size_t)(b * Sn + qrow0) * HIDn + h * Dn;
    {
        const int ar = tid >> 1, dc4 = (tid & 1) * 4;
#pragma unroll
        for (int dch = 0; dch < Dn; dch += 8) {
            float4 q = *(const float4*)(Qg + (size_t)ar * HIDn + dch + dc4);
            const int d = dch + dc4;
            Qs[(d + 0) * 136 + ar] = f2tf32(q.x);
            Qs[(d + 1) * 136 + ar] = f2tf32(q.y);
            Qs[(d + 2) * 136 + ar] = f2tf32(q.z);
            Qs[(d + 3) * 136 + ar] = f2tf32(q.w);
        }
    }
    __syncthreads();

    float m_i[4][2], l_i[4][2];
#pragma unroll
    for (int mi = 0; mi < 4; mi++) {
        m_i[mi][0] = m_i[mi][1] = -1e30f;
        l_i[mi][0] = l_i[mi][1] = 0.f;
    }
    float o[4][4][4] = {};

    const float SCALE = 0.0883883476483184f;   // 1/sqrt(128)
    const int kcolL = tid >> 1, dbase = (tid & 1) * 4;   // K-slab loader mapping
    const int vr = tid >> 5,  vc4 = (tid & 31) * 4;      // V-slab loader mapping

    for (int kt = 0; kt < Sn / 128; kt++) {
        const float* Kg = g_K + (size_t)(b * Sn + kt * 128) * HIDn + h * Dn;
        const float* Vg = g_V + (size_t)(b * Sn + kt * 128) * HIDn + h * Dn;

        // ---- S = Q @ K^T over d (8 slabs of 16) ----
        float s[4][4][4] = {};
        {
            float4 k0 = *(const float4*)(Kg + (size_t)kcolL * HIDn + dbase);
            float4 k1 = *(const float4*)(Kg + (size_t)kcolL * HIDn + dbase + 8);
            stA_slab(KV, dbase, kcolL, k0, k1);
        }
        __syncthreads();
        int buf = 0;
        for (int slab = 1; slab <= 8; slab++) {
            float4 n0, n1;
            if (slab < 8) {
                n0 = *(const float4*)(Kg + (size_t)kcolL * HIDn + slab * 16 + dbase);
                n1 = *(const float4*)(Kg + (size_t)kcolL * HIDn + slab * 16 + dbase + 8);
            }
            compute_slab16(Qs + (slab - 1) * 16 * 136, KV + buf * 2176, s, wm, wn, g, tig);
            if (slab < 8) stA_slab(KV + (buf ^ 1) * 2176, dbase, kcolL, n0, n1);
            __syncthreads();
            buf ^= 1;
        }

        // ---- online softmax: scale, row max (intra-warp + cross-warp) ----
        float alpha[4][2];
#pragma unroll
        for (int mi = 0; mi < 4; mi++)
#pragma unroll
            for (int hf = 0; hf < 2; hf++) {
                float pm = -1e30f;
#pragma unroll
                for (int ni = 0; ni < 4; ni++) {
                    s[mi][ni][hf * 2 + 0] *= SCALE;
                    s[mi][ni][hf * 2 + 1] *= SCALE;
                    pm = fmaxf(pm, fmaxf(s[mi][ni][hf * 2], s[mi][ni][hf * 2 + 1]));
                }
                pm = fmaxf(pm, __shfl_xor_sync(0xffffffffu, pm, 1));
                pm = fmaxf(pm, __shfl_xor_sync(0xffffffffu, pm, 2));
                if (tig == 0) redm[wnidx * 128 + wm + mi * 16 + g + 8 * hf] = pm;
            }
        __syncthreads();
#pragma unroll
        for (int mi = 0; mi < 4; mi++)
#pragma unroll
            for (int hf = 0; hf < 2; hf++) {
                const int row = wm + mi * 16 + g + 8 * hf;
                float rm = fmaxf(fmaxf(redm[row], redm[128 + row]),
                                 fmaxf(redm[256 + row], redm[384 + row]));
                float mn = fmaxf(m_i[mi][hf], rm);
                alpha[mi][hf] = __expf(m_i[mi][hf] - mn);
                m_i[mi][hf] = mn;
            }

        // ---- P = exp(S - m), store to Ps (A-layout), partial row sums, rescale O ----
#pragma unroll
        for (int mi = 0; mi < 4; mi++)
#pragma unroll
            for (int hf = 0; hf < 2; hf++) {
                const int row = wm + mi * 16 + g + 8 * hf;
                float ps = 0.f;
#pragma unroll
                for (int ni = 0; ni < 4; ni++) {
                    const int c = wn + ni * 8 + 2 * tig;
                    float p0 = __expf(s[mi][ni][hf * 2 + 0] - m_i[mi][hf]);
                    float p1 = __expf(s[mi][ni][hf * 2 + 1] - m_i[mi][hf]);
                    ps += p0 + p1;
                    Ps[(c + 0) * 136 + row] = f2tf32(p0);
                    Ps[(c + 1) * 136 + row] = f2tf32(p1);
                    o[mi][ni][hf * 2 + 0] *= alpha[mi][hf];
                    o[mi][ni][hf * 2 + 1] *= alpha[mi][hf];
                }
                ps += __shfl_xor_sync(0xffffffffu, ps, 1);
                ps += __shfl_xor_sync(0xffffffffu, ps, 2);
                if (tig == 0) reds[wnidx * 128 + row] = ps;
            }
        __syncthreads();
#pragma unroll
        for (int mi = 0; mi < 4; mi++)
#pragma unroll
            for (int hf = 0; hf < 2; hf++) {
                const int row = wm + mi * 16 + g + 8 * hf;
                float rs = reds[row] + reds[128 + row] + reds[256 + row] + reds[384 + row];
                l_i[mi][hf] = l_i[mi][hf] * alpha[mi][hf] + rs;
            }

        // ---- O += P @ V over kcol (8 slabs of 16) ----
        {
            float4 v0 = *(const float4*)(Vg + (size_t)vr * HIDn + vc4);
            float4 v1 = *(const float4*)(Vg + (size_t)(vr + 8) * HIDn + vc4);
            stB_slab(KV, vr, vc4, v0, v1);
        }
        __syncthreads();
        buf = 0;
        for (int slab = 1; slab <= 8; slab++) {
            float4 n0, n1;
            if (slab < 8) {
                n0 = *(const float4*)(Vg + (size_t)(slab * 16 + vr) * HIDn + vc4);
                n1 = *(const float4*)(Vg + (size_t)(slab * 16 + vr + 8) * HIDn + vc4);
            }
            compute_slab16(Ps + (slab - 1) * 16 * 136, KV + buf * 2176, o, wm, wn, g, tig);
            if (slab < 8) stB_slab(KV + (buf ^ 1) * 2176, vr, vc4, n0, n1);
            __syncthreads();
            buf ^= 1;
        }
    }

    // ---- normalize + GSA blend epilogue ----
    const float blend = g_scal[1];
    const float ob = 1.f - blend;
    float* Cb = g_CTX + (size_t)b * Sn * HIDn + h * Dn;
#pragma unroll
    for (int mi = 0; mi < 4; mi++)
#pragma unroll
        for (int hf = 0; hf < 2; hf++) {
            const int r = qrow0 + wm + mi * 16 + g + 8 * hf;
            const float invl = 1.f / l_i[mi][hf];
            const float4 qa0 = *(const float4*)&g_qa[((size_t)bh * Sn + r) * NSn];
            const float4 qa1 = *(const float4*)&g_qa[((size_t)bh * Sn + r) * NSn + 4];
            float wq[8];
            wq[0] = qa0.x * ampsm[0]; wq[1] = qa0.y * ampsm[1];
            wq[2] = qa0.z * ampsm[2]; wq[3] = qa0.w * ampsm[3];
            wq[4] = qa1.x * ampsm[4]; wq[5] = qa1.y * ampsm[5];
            wq[6] = qa1.z * ampsm[6]; wq[7] = qa1.w * ampsm[7];
            float den = 1e-8f;
#pragma unroll
            for (int n = 0; n < 8; n++) den += wq[n] * sksm[n];
            const float invden = 1.f / den;
#pragma unroll
            for (int ni = 0; ni < 4; ni++) {
                const int c = wn + ni * 8 + 2 * tig;
                float dg0 = 0.f, dg1 = 0.f;
#pragma unroll
                for (int n = 0; n < 8; n++) {
                    dg0 += wq[n] * Msm[n * 128 + c];
                    dg1 += wq[n] * Msm[n * 128 + c + 1];
                }
                const float a0 = o[mi][ni][hf * 2 + 0] * invl;
                const float a1 = o[mi][ni][hf * 2 + 1] * invl;
                *(float2*)&Cb[(size_t)r * HIDn + c] =
                    make_float2(ob * a0 + blend * dg0 * invden,
                                ob * a1 + blend * dg1 * invden);
            }
        }
}

// ---------------- launch ----------------
extern "C" void kernel_launch(void* const* d_in, const int* in_sizes, int n_in,
                              void* d_out, int out_size)
{
    (void)in_sizes; (void)n_in; (void)out_size;
    const float* hs   = (const float*)d_in[0];
    const float* Wq   = (const float*)d_in[1];
    const float* Wk   = (const float*)d_in[2];
    const float* Wv   = (const float*)d_in[3];
    const float* Wo   = (const float*)d_in[4];
    const float* spos = (const float*)d_in[5];
    const float* sdir = (const float*)d_in[6];
    const float* lsc  = (const float*)d_in[7];
    const float* lam  = (const float*)d_in[8];
    const float* dstr = (const float*)d_in[9];
    const float* gstr = (const float*)d_in[10];
    float* out = (float*)d_out;

    cudaFuncSetAttribute(flash_attn_kernel,
                         cudaFuncAttributeMaxDynamicSharedMemorySize, FLASH_SMEM_BYTES);

    prep_kernel<<<1, 128>>>(spos, sdir, lsc, lam, dstr, gstr);
    gemm_qkv<<<dim3(16, 16, 3), 256>>>(hs, Wq, Wk, Wv);
    affinity_kernel<<<dim3(4096, 1, 2), 256>>>();
    ksum_kernel<<<BHn * NCHUNK, 128>>>();
    flash_attn_kernel<<<dim3(Sn / 128, BHn), 256, FLASH_SMEM_BYTES>>>();
    gemm_out<<<dim3(16, 16), 256>>>(Wo, out);
}